// round 14
// baseline (speedup 1.0000x reference)
#include <cuda_runtime.h>
#include <cuda_bf16.h>
#include <stdint.h>
#include <math.h>

// Problem constants
#define VD 16384
#define ED 1024
#define HD 1024
#define H2 2048
#define LD 2
#define BD 128
#define TD 256
#define SD 64
#define TB 32768   // B*T
#define NG 3072    // fused gate+cand projection width

// ---------------- scratch (__device__ globals; no allocations allowed) -------------
__device__ float g_XGC[(size_t)TB * NG];   // layer-0 x-projections [T,B,3072]
__device__ float g_O1 [(size_t)TB * HD];   // layer-1 fp32 outputs (NCE input)
__device__ __nv_bfloat16 g_h0b [BD * HD];  // layer-0 h (bf16 shadow, mma operand)
__device__ __nv_bfloat16 g_h1b [BD * HD];  // layer-1 h
__device__ __nv_bfloat16 g_RH0b[BD * HD];
__device__ __nv_bfloat16 g_RH1b[BD * HD];
__device__ float g_sampWT[HD * SD];
__device__ float g_sampB [SD];
__device__ int   g_rowidx[TB];
__device__ unsigned g_barcnt;

__device__ __nv_bfloat16 g_Ab  [(size_t)TB * HD];  // X in bf16 (layer-0 A operand)
__device__ __nv_bfloat16 g_Eb  [(size_t)VD * ED];
__device__ __nv_bfloat16 g_WbTw[(size_t)HD * HD];  // win^T bf16
__device__ __nv_bfloat16 g_WbT0[(size_t)NG * HD];  // [Wxg0|Wxc0]^T bf16

__device__ __forceinline__ float softplusf(float x) {
    return fmaxf(x, 0.f) + log1pf(expf(-fabsf(x)));
}

// ---------------- PTX helpers ----------------
__device__ __forceinline__ uint32_t s2u(const void* p) {
    uint32_t a;
    asm("{ .reg .u64 t; cvta.to.shared.u64 t, %1; cvt.u32.u64 %0, t; }" : "=r"(a) : "l"(p));
    return a;
}
__device__ __forceinline__ void cp16(uint32_t dst, const void* src) {
    asm volatile("cp.async.cg.shared.global [%0], [%1], 16;" :: "r"(dst), "l"(src));
}
#define CP_COMMIT() asm volatile("cp.async.commit_group;" ::: "memory")
#define CP_WAIT(n)  asm volatile("cp.async.wait_group %0;" :: "n"(n) : "memory")
__device__ __forceinline__ void cp_wait_dyn(bool one) {
    if (one) CP_WAIT(1); else CP_WAIT(0);
}

__device__ __forceinline__ void ldmatrix_x4(uint32_t& r0, uint32_t& r1,
                                            uint32_t& r2, uint32_t& r3, uint32_t addr) {
    asm volatile("ldmatrix.sync.aligned.m8n8.x4.shared.b16 {%0,%1,%2,%3}, [%4];"
                 : "=r"(r0), "=r"(r1), "=r"(r2), "=r"(r3) : "r"(addr));
}
__device__ __forceinline__ void ldmatrix_x2(uint32_t& r0, uint32_t& r1, uint32_t addr) {
    asm volatile("ldmatrix.sync.aligned.m8n8.x2.shared.b16 {%0,%1}, [%2];"
                 : "=r"(r0), "=r"(r1) : "r"(addr));
}
__device__ __forceinline__ void mma16816(float* d, const uint32_t* a, const uint32_t* b) {
    asm volatile("mma.sync.aligned.m16n8k16.row.col.f32.bf16.bf16.f32 "
                 "{%0,%1,%2,%3},{%4,%5,%6,%7},{%8,%9},{%0,%1,%2,%3};"
                 : "+f"(d[0]), "+f"(d[1]), "+f"(d[2]), "+f"(d[3])
                 : "r"(a[0]), "r"(a[1]), "r"(a[2]), "r"(a[3]), "r"(b[0]), "r"(b[1]));
}

// single-counter software grid barrier (round-12 proven form; DO NOT CHANGE)
__device__ __forceinline__ void gsync(unsigned target) {
    __syncthreads();
    if (threadIdx.x == 0) {
        __threadfence();
        atomicAdd(&g_barcnt, 1u);
        while (*(volatile unsigned*)&g_barcnt < target) __nanosleep(16);
        __threadfence();
    }
    __syncthreads();
}

// ---------------- upfront fused kernel: setup + emb->bf16 + weight transposes -------
__global__ void k_convW(const int* __restrict__ input_data, float* out, int out_size,
                        const float* __restrict__ emb, const float* __restrict__ win,
                        const float* __restrict__ Wxg, const float* __restrict__ Wxc)
{
    const int bx = blockIdx.x;
    const int tid = threadIdx.x;
    if (bx < 128) {
        if (bx == 0 && tid == 0) {
            g_barcnt = 0u;
            for (int i = 0; i < out_size; i++) out[i] = 0.f;
        }
        int r = bx * 256 + tid;
        int t = r >> 7, b = r & 127;
        g_rowidx[r] = input_data[b * TD + t];
    } else if (bx < 128 + 16384) {
        int i = (bx - 128) * 256 + tid;
        float4 v = ((const float4*)emb)[i];
        __nv_bfloat162* o = (__nv_bfloat162*)g_Eb;
        o[2 * i + 0] = __floats2bfloat162_rn(v.x, v.y);
        o[2 * i + 1] = __floats2bfloat162_rn(v.z, v.w);
    } else {
        __shared__ float tile[32][33];
        const int tx = tid & 31, ty = tid >> 5;   // 32 x 8
        if (bx < 128 + 16384 + 1024) {
            int idx = bx - (128 + 16384);
            int n0 = (idx & 31) * 32, k0 = (idx >> 5) * 32;
            #pragma unroll
            for (int j = 0; j < 4; j++)
                tile[ty + 8 * j][tx] = win[(size_t)(k0 + ty + 8 * j) * HD + n0 + tx];
            __syncthreads();
            #pragma unroll
            for (int j = 0; j < 4; j++)
                g_WbTw[(size_t)(n0 + ty + 8 * j) * HD + k0 + tx] =
                    __float2bfloat16(tile[tx][ty + 8 * j]);
        } else {
            int idx = bx - (128 + 16384 + 1024);   // 0..3071 (layer-0 only)
            int n0 = (idx % 96) * 32, k0 = (idx / 96) * 32;
            #pragma unroll
            for (int j = 0; j < 4; j++) {
                int k = k0 + ty + 8 * j;
                int n = n0 + tx;
                tile[ty + 8 * j][tx] = (n < 2048) ? Wxg[(size_t)k * H2 + n]
                                                  : Wxc[(size_t)k * HD + (n - 2048)];
            }
            __syncthreads();
            #pragma unroll
            for (int j = 0; j < 4; j++)
                g_WbT0[(size_t)(n0 + ty + 8 * j) * HD + k0 + tx] =
                    __float2bfloat16(tile[tx][ty + 8 * j]);
        }
    }
}

__global__ void k_gather_samp(const int* __restrict__ nce,
                              const float* __restrict__ sw,
                              const float* __restrict__ sb) {
    int s = blockIdx.x;
    int row = nce[s];
    const float* src = sw + (size_t)row * HD;
    for (int k = threadIdx.x; k < HD; k += blockDim.x)
        g_sampWT[k * SD + s] = src[k];
    if (threadIdx.x == 0) g_sampB[s] = sb[row];
}

// ---------------- bf16 mma.sync GEMM (fp32 or bf16 output) ----------------
#define LDP 40

template<bool GATHER, bool BIAS, bool OB16>
__global__ __launch_bounds__(256)
void k_mgemm(const __nv_bfloat16* __restrict__ A, const __nv_bfloat16* __restrict__ BT,
             const float* __restrict__ bias, float* __restrict__ Cf,
             __nv_bfloat16* __restrict__ Cb, int N, const int* __restrict__ gidx)
{
    __shared__ __align__(16) __nv_bfloat16 sA[2][128 * LDP];
    __shared__ __align__(16) __nv_bfloat16 sB[2][128 * LDP];

    const int tid = threadIdx.x;
    const int rowBase = blockIdx.y * 128;
    const int colBase = blockIdx.x * 128;

    const int lrow = tid & 127;
    const bool isB = tid >= 128;
    const __nv_bfloat16* src;
    if (isB) {
        src = BT + (size_t)(colBase + lrow) * 1024;
    } else {
        size_t ar = GATHER ? (size_t)gidx[rowBase + lrow] : (size_t)(rowBase + lrow);
        src = A + ar * 1024;
    }
    uint32_t dst0 = s2u(isB ? (const void*)&sB[0][lrow * LDP] : (const void*)&sA[0][lrow * LDP]);
    uint32_t dst1 = s2u(isB ? (const void*)&sB[1][lrow * LDP] : (const void*)&sA[1][lrow * LDP]);

    const int wid = tid >> 5, lane = tid & 31;
    const int mb = (wid & 1) * 64;
    const int nb = (wid >> 1) * 32;
    const int arow_l = (lane & 7) + ((lane >> 3) & 1) * 8;
    const int acol_l = (lane >> 4) * 8;
    const int brow_l = (lane & 7) + (lane >> 4) * 8;
    const int bcol_l = ((lane >> 3) & 1) * 8;
    const uint32_t aS0 = s2u(sA[0]), aS1 = s2u(sA[1]);
    const uint32_t bS0 = s2u(sB[0]), bS1 = s2u(sB[1]);

    float acc[4][4][4];
    #pragma unroll
    for (int mt = 0; mt < 4; mt++)
        #pragma unroll
        for (int nt = 0; nt < 4; nt++)
            #pragma unroll
            for (int q = 0; q < 4; q++) acc[mt][nt][q] = 0.f;

    const int S = 32;
    {
        const __nv_bfloat16* p = src;
        #pragma unroll
        for (int c = 0; c < 4; c++) cp16(dst0 + c * 16, p + c * 8);
        CP_COMMIT();
    }

    for (int s = 0; s < S; s++) {
        if (s + 1 < S) {
            uint32_t d = ((s + 1) & 1) ? dst1 : dst0;
            const __nv_bfloat16* p = src + (s + 1) * 32;
            #pragma unroll
            for (int c = 0; c < 4; c++) cp16(d + c * 16, p + c * 8);
            CP_COMMIT();
            CP_WAIT(1);
        } else {
            CP_WAIT(0);
        }
        __syncthreads();

        const uint32_t aS = (s & 1) ? aS1 : aS0;
        const uint32_t bS = (s & 1) ? bS1 : bS0;
        #pragma unroll
        for (int kk = 0; kk < 32; kk += 16) {
            uint32_t af[4][4];
            #pragma unroll
            for (int mt = 0; mt < 4; mt++) {
                uint32_t ad = aS + (uint32_t)(((mb + mt * 16 + arow_l) * LDP) + kk + acol_l) * 2u;
                ldmatrix_x4(af[mt][0], af[mt][1], af[mt][2], af[mt][3], ad);
            }
            uint32_t bf[2][4];
            #pragma unroll
            for (int nt2 = 0; nt2 < 2; nt2++) {
                uint32_t bd = bS + (uint32_t)(((nb + nt2 * 16 + brow_l) * LDP) + kk + bcol_l) * 2u;
                ldmatrix_x4(bf[nt2][0], bf[nt2][1], bf[nt2][2], bf[nt2][3], bd);
            }
            #pragma unroll
            for (int mt = 0; mt < 4; mt++)
                #pragma unroll
                for (int nt = 0; nt < 4; nt++)
                    mma16816(acc[mt][nt], af[mt], &bf[nt >> 1][(nt & 1) * 2]);
        }
        __syncthreads();
    }

    const int erow = lane >> 2;
    const int ecol = (lane & 3) * 2;
    #pragma unroll
    for (int mt = 0; mt < 4; mt++) {
        #pragma unroll
        for (int nt = 0; nt < 4; nt++) {
            int r0 = rowBase + mb + mt * 16 + erow;
            int c0 = colBase + nb + nt * 8 + ecol;
            float b0 = 0.f, b1 = 0.f;
            if (BIAS) { b0 = bias[c0]; b1 = bias[c0 + 1]; }
            float v00 = acc[mt][nt][0] + b0, v01 = acc[mt][nt][1] + b1;
            float v10 = acc[mt][nt][2] + b0, v11 = acc[mt][nt][3] + b1;
            if (OB16) {
                __nv_bfloat162 p0 = __floats2bfloat162_rn(v00, v01);
                __nv_bfloat162 p1 = __floats2bfloat162_rn(v10, v11);
                *(__nv_bfloat162*)&Cb[(size_t)r0 * N + c0] = p0;
                *(__nv_bfloat162*)&Cb[(size_t)(r0 + 8) * N + c0] = p1;
            } else {
                *(float2*)&Cf[(size_t)r0 * N + c0] = make_float2(v00, v01);
                *(float2*)&Cf[(size_t)(r0 + 8) * N + c0] = make_float2(v10, v11);
            }
        }
    }
}

// ---------------- 2-layer wavefront MI-GRU recurrence --------------------------------
// 128 CTAs x 256 threads. CTA c owns cols [8c,8c+8) of: r-gate, u-gate(+1024), cand —
// for BOTH layers, plus the 24 layer-1 x-projection columns it consumes.
// Wavefront step s: phase A = gate(L0 step s, L1 step s-1); phase B = cand(both);
// phase C = per-step projection xgc1 = h0 @ Wx1slice, result kept in registers.
// h state lives in registers (producer lane == consumer lane). 2 barriers/step.
__global__ __launch_bounds__(256)
void k_wave(const float* __restrict__ Whg, const float* __restrict__ Whc,
            const float* __restrict__ Wxg, const float* __restrict__ Wxc,
            const float* __restrict__ XGC,
            const float* __restrict__ ag, const float* __restrict__ b1g,
            const float* __restrict__ b2g, const float* __restrict__ bg,
            const float* __restrict__ ac, const float* __restrict__ b1c,
            const float* __restrict__ b2c, const float* __restrict__ bcv,
            float* __restrict__ O1)
{
    extern __shared__ __nv_bfloat16 sm[];
    // offsets in bf16 elems
    __nv_bfloat16* Wg0 = sm;                  // 16x1032
    __nv_bfloat16* Wc0 = sm + 16512;          // 8x1032
    __nv_bfloat16* Wg1 = sm + 24768;          // 16x1032
    __nv_bfloat16* Wc1 = sm + 41280;          // 8x1032
    __nv_bfloat16* Wx1 = sm + 49536;          // 24x1032
    __nv_bfloat16* stg = sm + 74304;          // 2 stages x 128x136

    const int cta = blockIdx.x;
    const int tid = threadIdx.x;
    const int wid = tid >> 5, lane = tid & 31;
    const int col0 = cta * 8;

    // ---- weight slices -> SMEM bf16 ----
    const float* Whg1 = Whg + (size_t)HD * H2;
    const float* Whc1 = Whc + (size_t)HD * HD;
    const float* Wxg1 = Wxg + (size_t)HD * H2;
    const float* Wxc1 = Wxc + (size_t)HD * HD;
    for (int i = tid; i < 16 * 1024; i += 256) {
        int n = i & 15, k = i >> 4;
        int col = (n < 8) ? (col0 + n) : (1024 + col0 + (n - 8));
        Wg0[n * 1032 + k] = __float2bfloat16(Whg[(size_t)k * H2 + col]);
        Wg1[n * 1032 + k] = __float2bfloat16(Whg1[(size_t)k * H2 + col]);
    }
    for (int i = tid; i < 8 * 1024; i += 256) {
        int n = i & 7, k = i >> 3;
        Wc0[n * 1032 + k] = __float2bfloat16(Whc[(size_t)k * HD + col0 + n]);
        Wc1[n * 1032 + k] = __float2bfloat16(Whc1[(size_t)k * HD + col0 + n]);
    }
    for (int i = tid; i < 24 * 1024; i += 256) {
        int n = i % 24, k = i / 24;
        float v;
        if (n < 8)       v = Wxg1[(size_t)k * H2 + col0 + n];
        else if (n < 16) v = Wxg1[(size_t)k * H2 + 1024 + col0 + (n - 8)];
        else             v = Wxc1[(size_t)k * HD + col0 + (n - 16)];
        Wx1[n * 1032 + k] = __float2bfloat16(v);
    }

    const int arow_l = (lane & 7) + ((lane >> 3) & 1) * 8;
    const int acol_l = (lane >> 4) * 8;
    const int brow_l = (lane & 7) + (lane >> 4) * 8;
    const int bcol_l = ((lane >> 3) & 1) * 8;
    const int l16 = lane & 15;

    const uint32_t stB  = s2u(stg);
    const uint32_t wg0B = s2u(Wg0);
    const uint32_t wc0B = s2u(Wc0);
    const uint32_t wg1B = s2u(Wg1);
    const uint32_t wc1B = s2u(Wc1);
    const uint32_t wx1B = s2u(Wx1);

    const int erow = lane >> 2;
    const int ecol = (lane & 3) * 2;
    const int r0 = wid * 16 + erow;

    // per-lane constants, [layer][j]
    float agr[2][2], b1r[2][2], b2r[2][2], bgr[2][2];
    float agu[2][2], b1u[2][2], b2u[2][2], bgu[2][2];
    float acv[2][2], b1cv[2][2], b2cv[2][2], bcvv[2][2];
    #pragma unroll
    for (int L = 0; L < 2; L++) {
        #pragma unroll
        for (int j = 0; j < 2; j++) {
            int cr = col0 + ecol + j;
            int cu = 1024 + cr;
            agr[L][j] = ag[L * H2 + cr]; b1r[L][j] = b1g[L * H2 + cr];
            b2r[L][j] = b2g[L * H2 + cr]; bgr[L][j] = bg[L * H2 + cr];
            agu[L][j] = ag[L * H2 + cu]; b1u[L][j] = b1g[L * H2 + cu];
            b2u[L][j] = b2g[L * H2 + cu]; bgu[L][j] = bg[L * H2 + cu];
            acv[L][j] = ac[L * HD + cr]; b1cv[L][j] = b1c[L * HD + cr];
            b2cv[L][j] = b2c[L * HD + cr]; bcvv[L][j] = bcv[L * HD + cr];
        }
    }

    const int srow = tid & 127;
    const int scb  = (tid >> 7) * 8;
    const uint32_t sdst_off = (uint32_t)(srow * 272 + scb * 16);

    // register-resident state
    float hp0[2][2] = {{0.f, 0.f}, {0.f, 0.f}};   // layer-0 h at (r0+half*8, col0+ecol+j)
    float hp1[2][2] = {{0.f, 0.f}, {0.f, 0.f}};
    float px[3][4];                                // xgc1 frags: [0]=r, [1]=u, [2]=cand
    #pragma unroll
    for (int nt = 0; nt < 3; nt++)
        #pragma unroll
        for (int q = 0; q < 4; q++) px[nt][q] = 0.f;

    // zero h shadows (CTA owns 2048 bf16 of each)
    for (int i = tid; i < 1024; i += 256) {
        __stcg((uint32_t*)(g_h0b + cta * 2048) + i, 0u);
        __stcg((uint32_t*)(g_h1b + cta * 2048) + i, 0u);
    }
    unsigned bar = 1;
    gsync(bar * 128u);

    for (int s = 0; s <= TD; s++) {
        const bool L0on = (s < TD);
        const bool L1on = (s >= 1);
        const float* Xt0 = XGC + (size_t)s * BD * NG;
        float u0[2][2], u1[2][2];

        // ================= phase A: gates (L0 step s, L1 step s-1) =================
        {
            float2 gxr0[2], gxu0[2];
            if (L0on) {
                #pragma unroll
                for (int half = 0; half < 2; half++) {
                    int row = r0 + half * 8;
                    gxr0[half] = __ldcg((const float2*)(Xt0 + (size_t)row * NG + col0 + ecol));
                    gxu0[half] = __ldcg((const float2*)(Xt0 + (size_t)row * NG + 1024 + col0 + ecol));
                }
            }

            float acc0[2][4], acc1[2][4];
            #pragma unroll
            for (int nt = 0; nt < 2; nt++)
                #pragma unroll
                for (int q = 0; q < 4; q++) { acc0[nt][q] = 0.f; acc1[nt][q] = 0.f; }

            const int lo = L0on ? 0 : 8;
            const int hi = L1on ? 16 : 8;
            // prologue: issue two chunks
            #pragma unroll
            for (int p = 0; p < 2; p++) {
                int ch = lo + p;
                const __nv_bfloat16* base = (ch < 8) ? g_h0b : g_h1b;
                const __nv_bfloat16* src = base + (size_t)srow * 1024 + (ch & 7) * 128 + scb * 8;
                uint32_t dst = stB + (uint32_t)(ch & 1) * 34816u + sdst_off;
                #pragma unroll
                for (int c = 0; c < 8; c++) cp16(dst + c * 16, src + c * 8);
                CP_COMMIT();
            }
            for (int i = lo; i < hi; i++) {
                cp_wait_dyn(i + 1 < hi);
                __syncthreads();
                uint32_t aB = stB + (uint32_t)(i & 1) * 34816u;
                int kgB = (i & 7) * 128;
                if (i < 8) {
                    #pragma unroll
                    for (int ks = 0; ks < 8; ks++) {
                        int kloc = ks * 16;
                        uint32_t af[4];
                        ldmatrix_x4(af[0], af[1], af[2], af[3],
                            aB + (uint32_t)((wid * 16 + arow_l) * 272 + (kloc + acol_l) * 2));
                        uint32_t bf[4];
                        ldmatrix_x4(bf[0], bf[1], bf[2], bf[3],
                            wg0B + (uint32_t)(brow_l * 2064 + (kgB + kloc + bcol_l) * 2));
                        mma16816(acc0[0], af, &bf[0]);
                        mma16816(acc0[1], af, &bf[2]);
                    }
                } else {
                    #pragma unroll
                    for (int ks = 0; ks < 8; ks++) {
                        int kloc = ks * 16;
                        uint32_t af[4];
                        ldmatrix_x4(af[0], af[1], af[2], af[3],
                            aB + (uint32_t)((wid * 16 + arow_l) * 272 + (kloc + acol_l) * 2));
                        uint32_t bf[4];
                        ldmatrix_x4(bf[0], bf[1], bf[2], bf[3],
                            wg1B + (uint32_t)(brow_l * 2064 + (kgB + kloc + bcol_l) * 2));
                        mma16816(acc1[0], af, &bf[0]);
                        mma16816(acc1[1], af, &bf[2]);
                    }
                }
                __syncthreads();
                if (i + 2 < hi) {
                    int ch = i + 2;
                    const __nv_bfloat16* base = (ch < 8) ? g_h0b : g_h1b;
                    const __nv_bfloat16* src = base + (size_t)srow * 1024 + (ch & 7) * 128 + scb * 8;
                    uint32_t dst = stB + (uint32_t)(ch & 1) * 34816u + sdst_off;
                    #pragma unroll
                    for (int c = 0; c < 8; c++) cp16(dst + c * 16, src + c * 8);
                    CP_COMMIT();
                }
            }

            if (L0on) {
                #pragma unroll
                for (int half = 0; half < 2; half++) {
                    int row = r0 + half * 8;
                    float gh0 = acc0[0][half * 2 + 0], gh1 = acc0[0][half * 2 + 1];
                    float z0 = agr[0][0] * gxr0[half].x * gh0 + b1r[0][0] * gxr0[half].x + b2r[0][0] * gh0 + bgr[0][0];
                    float z1 = agr[0][1] * gxr0[half].y * gh1 + b1r[0][1] * gxr0[half].y + b2r[0][1] * gh1 + bgr[0][1];
                    float s0 = 1.f / (1.f + expf(-z0));
                    float s1 = 1.f / (1.f + expf(-z1));
                    __nv_bfloat162 p = __floats2bfloat162_rn(s0 * hp0[half][0], s1 * hp0[half][1]);
                    __stcg((uint32_t*)(g_RH0b + (size_t)row * 1024 + col0 + ecol), *(uint32_t*)&p);
                    float uh0 = acc0[1][half * 2 + 0], uh1 = acc0[1][half * 2 + 1];
                    float y0 = agu[0][0] * gxu0[half].x * uh0 + b1u[0][0] * gxu0[half].x + b2u[0][0] * uh0 + bgu[0][0];
                    float y1 = agu[0][1] * gxu0[half].y * uh1 + b1u[0][1] * gxu0[half].y + b2u[0][1] * uh1 + bgu[0][1];
                    u0[half][0] = 1.f / (1.f + expf(-y0));
                    u0[half][1] = 1.f / (1.f + expf(-y1));
                }
            }
            if (L1on) {
                #pragma unroll
                for (int half = 0; half < 2; half++) {
                    int row = r0 + half * 8;
                    float gx0 = px[0][half * 2 + 0], gx1 = px[0][half * 2 + 1];
                    float gh0 = acc1[0][half * 2 + 0], gh1 = acc1[0][half * 2 + 1];
                    float z0 = agr[1][0] * gx0 * gh0 + b1r[1][0] * gx0 + b2r[1][0] * gh0 + bgr[1][0];
                    float z1 = agr[1][1] * gx1 * gh1 + b1r[1][1] * gx1 + b2r[1][1] * gh1 + bgr[1][1];
                    float s0 = 1.f / (1.f + expf(-z0));
                    float s1 = 1.f / (1.f + expf(-z1));
                    __nv_bfloat162 p = __floats2bfloat162_rn(s0 * hp1[half][0], s1 * hp1[half][1]);
                    __stcg((uint32_t*)(g_RH1b + (size_t)row * 1024 + col0 + ecol), *(uint32_t*)&p);
                    float ux0 = px[1][half * 2 + 0], ux1 = px[1][half * 2 + 1];
                    float uh0 = acc1[1][half * 2 + 0], uh1 = acc1[1][half * 2 + 1];
                    float y0 = agu[1][0] * ux0 * uh0 + b1u[1][0] * ux0 + b2u[1][0] * uh0 + bgu[1][0];
                    float y1 = agu[1][1] * ux1 * uh1 + b1u[1][1] * ux1 + b2u[1][1] * uh1 + bgu[1][1];
                    u1[half][0] = 1.f / (1.f + expf(-y0));
                    u1[half][1] = 1.f / (1.f + expf(-y1));
                }
            }
        }
        bar++; gsync(bar * 128u);

        // ================= phase B: candidates + state update =================
        {
            float2 cx0[2];
            if (L0on) {
                #pragma unroll
                for (int half = 0; half < 2; half++) {
                    int row = r0 + half * 8;
                    cx0[half] = __ldcg((const float2*)(Xt0 + (size_t)row * NG + 2048 + col0 + ecol));
                }
            }

            float accC0[4] = {0.f, 0.f, 0.f, 0.f};
            float accC1[4] = {0.f, 0.f, 0.f, 0.f};
            const int lo = L0on ? 0 : 8;
            const int hi = L1on ? 16 : 8;
            #pragma unroll
            for (int p = 0; p < 2; p++) {
                int ch = lo + p;
                const __nv_bfloat16* base = (ch < 8) ? g_RH0b : g_RH1b;
                const __nv_bfloat16* src = base + (size_t)srow * 1024 + (ch & 7) * 128 + scb * 8;
                uint32_t dst = stB + (uint32_t)(ch & 1) * 34816u + sdst_off;
                #pragma unroll
                for (int c = 0; c < 8; c++) cp16(dst + c * 16, src + c * 8);
                CP_COMMIT();
            }
            for (int i = lo; i < hi; i++) {
                cp_wait_dyn(i + 1 < hi);
                __syncthreads();
                uint32_t aB = stB + (uint32_t)(i & 1) * 34816u;
                int kgB = (i & 7) * 128;
                if (i < 8) {
                    #pragma unroll
                    for (int ks = 0; ks < 8; ks++) {
                        int kloc = ks * 16;
                        uint32_t af[4];
                        ldmatrix_x4(af[0], af[1], af[2], af[3],
                            aB + (uint32_t)((wid * 16 + arow_l) * 272 + (kloc + acol_l) * 2));
                        uint32_t bf2[2];
                        ldmatrix_x2(bf2[0], bf2[1],
                            wc0B + (uint32_t)((l16 & 7) * 2064 + (kgB + kloc + (l16 >> 3) * 8) * 2));
                        mma16816(accC0, af, bf2);
                    }
                } else {
                    #pragma unroll
                    for (int ks = 0; ks < 8; ks++) {
                        int kloc = ks * 16;
                        uint32_t af[4];
                        ldmatrix_x4(af[0], af[1], af[2], af[3],
                            aB + (uint32_t)((wid * 16 + arow_l) * 272 + (kloc + acol_l) * 2));
                        uint32_t bf2[2];
                        ldmatrix_x2(bf2[0], bf2[1],
                            wc1B + (uint32_t)((l16 & 7) * 2064 + (kgB + kloc + (l16 >> 3) * 8) * 2));
                        mma16816(accC1, af, bf2);
                    }
                }
                __syncthreads();
                if (i + 2 < hi) {
                    int ch = i + 2;
                    const __nv_bfloat16* base = (ch < 8) ? g_RH0b : g_RH1b;
                    const __nv_bfloat16* src = base + (size_t)srow * 1024 + (ch & 7) * 128 + scb * 8;
                    uint32_t dst = stB + (uint32_t)(ch & 1) * 34816u + sdst_off;
                    #pragma unroll
                    for (int c = 0; c < 8; c++) cp16(dst + c * 16, src + c * 8);
                    CP_COMMIT();
                }
            }

            if (L0on) {
                #pragma unroll
                for (int half = 0; half < 2; half++) {
                    int row = r0 + half * 8;
                    float ch0 = accC0[half * 2 + 0], ch1 = accC0[half * 2 + 1];
                    float z0 = acv[0][0] * cx0[half].x * ch0 + b1cv[0][0] * cx0[half].x + b2cv[0][0] * ch0 + bcvv[0][0];
                    float z1 = acv[0][1] * cx0[half].y * ch1 + b1cv[0][1] * cx0[half].y + b2cv[0][1] * ch1 + bcvv[0][1];
                    float c0 = tanhf(z0), c1 = tanhf(z1);
                    float hn0 = u0[half][0] * hp0[half][0] + (1.f - u0[half][0]) * c0;
                    float hn1 = u0[half][1] * hp0[half][1] + (1.f - u0[half][1]) * c1;
                    hp0[half][0] = hn0; hp0[half][1] = hn1;
                    __nv_bfloat162 p = __floats2bfloat162_rn(hn0, hn1);
                    __stcg((uint32_t*)(g_h0b + (size_t)row * 1024 + col0 + ecol), *(uint32_t*)&p);
                }
            }
            if (L1on) {
                int t1 = s - 1;
                #pragma unroll
                for (int half = 0; half < 2; half++) {
                    int row = r0 + half * 8;
                    float cx0v = px[2][half * 2 + 0], cx1v = px[2][half * 2 + 1];
                    float ch0 = accC1[half * 2 + 0], ch1 = accC1[half * 2 + 1];
                    float z0 = acv[1][0] * cx0v * ch0 + b1cv[1][0] * cx0v + b2cv[1][0] * ch0 + bcvv[1][0];
                    float z1 = acv[1][1] * cx1v * ch1 + b1cv[1][1] * cx1v + b2cv[1][1] * ch1 + bcvv[1][1];
                    float c0 = tanhf(z0), c1 = tanhf(z1);
                    float hn0 = u1[half][0] * hp1[half][0] + (1.f - u1[half][0]) * c0;
                    float hn1 = u1[half][1] * hp1[half][1] + (1.f - u1[half][1]) * c1;
                    hp1[half][0] = hn0; hp1[half][1] = hn1;
                    __nv_bfloat162 p = __floats2bfloat162_rn(hn0, hn1);
                    __stcg((uint32_t*)(g_h1b + (size_t)row * 1024 + col0 + ecol), *(uint32_t*)&p);
                    *(float2*)(O1 + (size_t)t1 * BD * HD + (size_t)row * HD + col0 + ecol) =
                        make_float2(hn0, hn1);
                }
            }
        }
        bar++; gsync(bar * 128u);

        // ================= phase C: xgc1[s] = h0 @ Wx1slice (registers) ============
        if (L0on) {
            float accP[3][4];
            #pragma unroll
            for (int nt = 0; nt < 3; nt++)
                #pragma unroll
                for (int q = 0; q < 4; q++) accP[nt][q] = 0.f;

            #pragma unroll
            for (int p = 0; p < 2; p++) {
                const __nv_bfloat16* src = g_h0b + (size_t)srow * 1024 + p * 128 + scb * 8;
                uint32_t dst = stB + (uint32_t)(p & 1) * 34816u + sdst_off;
                #pragma unroll
                for (int c = 0; c < 8; c++) cp16(dst + c * 16, src + c * 8);
                CP_COMMIT();
            }
            for (int i = 0; i < 8; i++) {
                cp_wait_dyn(i + 1 < 8);
                __syncthreads();
                uint32_t aB = stB + (uint32_t)(i & 1) * 34816u;
                int kgB = i * 128;
                #pragma unroll
                for (int ks = 0; ks < 8; ks++) {
                    int kloc = ks * 16;
                    uint32_t af[4];
                    ldmatrix_x4(af[0], af[1], af[2], af[3],
                        aB + (uint32_t)((wid * 16 + arow_l) * 272 + (kloc + acol_l) * 2));
                    #pragma unroll
                    for (int nt = 0; nt < 3; nt++) {
                        uint32_t bx[2];
                        ldmatrix_x2(bx[0], bx[1],
                            wx1B + (uint32_t)((nt * 8 + (l16 & 7)) * 2064 +
                                              (kgB + kloc + (l16 >> 3) * 8) * 2));
                        mma16816(accP[nt], af, bx);
                    }
                }
                __syncthreads();
                if (i + 2 < 8) {
                    const __nv_bfloat16* src = g_h0b + (size_t)srow * 1024 + (i + 2) * 128 + scb * 8;
                    uint32_t dst = stB + (uint32_t)((i + 2) & 1) * 34816u + sdst_off;
                    #pragma unroll
                    for (int c = 0; c < 8; c++) cp16(dst + c * 16, src + c * 8);
                    CP_COMMIT();
                }
            }
            #pragma unroll
            for (int nt = 0; nt < 3; nt++)
                #pragma unroll
                for (int q = 0; q < 4; q++) px[nt][q] = accP[nt][q];
        }
        // no barrier needed after C (cross-CTA ordering covered by barriers above)
    }
}

// ---------------- NCE ----------------
__global__ __launch_bounds__(256)
void k_nce_samp(float* __restrict__ outsum)
{
    __shared__ float As[8][132];
    __shared__ float Bs[8][64];
    __shared__ float red[256];
    const int tid = threadIdx.x;
    const int rowBase = blockIdx.x * 128;

    const int arow = tid >> 1;
    const int acol = (tid & 1) << 2;
    int gi = rowBase + arow;
    size_t aoff = (size_t)((gi & 255) * BD + (gi >> 8)) * HD;

    const int brow = tid >> 5;
    const int bcl  = (tid & 31) << 1;
    const int ty = tid >> 4;
    const int tx = tid & 15;

    float acc[8][4];
    #pragma unroll
    for (int i = 0; i < 8; i++)
        #pragma unroll
        for (int j = 0; j < 4; j++) acc[i][j] = 0.f;

    for (int k0 = 0; k0 < HD; k0 += 8) {
        float4 av = *(const float4*)(g_O1 + aoff + k0 + acol);
        As[acol + 0][arow] = av.x;
        As[acol + 1][arow] = av.y;
        As[acol + 2][arow] = av.z;
        As[acol + 3][arow] = av.w;
        float2 bw = *(const float2*)(g_sampWT + (size_t)(k0 + brow) * SD + bcl);
        Bs[brow][bcl]     = bw.x;
        Bs[brow][bcl + 1] = bw.y;
        __syncthreads();
        #pragma unroll
        for (int k = 0; k < 8; k++) {
            float ar[8], br[4];
            *(float4*)&ar[0] = *(const float4*)&As[k][ty * 8];
            *(float4*)&ar[4] = *(const float4*)&As[k][ty * 8 + 4];
            *(float4*)&br[0] = *(const float4*)&Bs[k][tx * 4];
            #pragma unroll
            for (int i = 0; i < 8; i++)
                #pragma unroll
                for (int j = 0; j < 4; j++)
                    acc[i][j] += ar[i] * br[j];
        }
        __syncthreads();
    }

    float s = 0.f;
    #pragma unroll
    for (int j = 0; j < 4; j++) {
        float sbv = g_sampB[tx * 4 + j];
        #pragma unroll
        for (int i = 0; i < 8; i++)
            s += softplusf(acc[i][j] + sbv);
    }
    red[tid] = s;
    __syncthreads();
    for (int o = 128; o > 0; o >>= 1) {
        if (tid < o) red[tid] += red[tid + o];
        __syncthreads();
    }
    if (tid == 0) atomicAdd(outsum, red[0] * (1.f / 32768.f));
}

__global__ __launch_bounds__(256)
void k_nce_true(const int* __restrict__ targets, const float* __restrict__ sw,
                const float* __restrict__ sb, float* __restrict__ outsum)
{
    __shared__ float red[8];
    const int warp = threadIdx.x >> 5;
    const int lane = threadIdx.x & 31;
    const int i = blockIdx.x * 8 + warp;
    const int label = targets[i];
    const float* orow = g_O1 + (size_t)((i & 255) * BD + (i >> 8)) * HD;
    const float* wrow = sw + (size_t)label * HD;

    float s = 0.f;
    #pragma unroll
    for (int k0 = 0; k0 < HD; k0 += 128) {
        float4 a = *(const float4*)(orow + k0 + lane * 4);
        float4 w = *(const float4*)(wrow + k0 + lane * 4);
        s += a.x * w.x + a.y * w.y + a.z * w.z + a.w * w.w;
    }
    #pragma unroll
    for (int o = 16; o > 0; o >>= 1) s += __shfl_xor_sync(0xffffffffu, s, o);
    if (lane == 0) {
        float logit = s + sb[label];
        red[warp] = softplusf(-logit);
    }
    __syncthreads();
    if (threadIdx.x == 0) {
        float t = 0.f;
        #pragma unroll
        for (int w = 0; w < 8; w++) t += red[w];
        atomicAdd(outsum, t * (1.f / 32768.f));
    }
}

// ---------------- launch ----------------
extern "C" void kernel_launch(void* const* d_in, const int* in_sizes, int n_in,
                              void* d_out, int out_size)
{
    const int*   input_data = (const int*)  d_in[0];
    const int*   targets    = (const int*)  d_in[1];
    const int*   nce        = (const int*)  d_in[2];
    const float* embedding  = (const float*)d_in[3];
    const float* win        = (const float*)d_in[4];
    const float* bin_       = (const float*)d_in[5];
    const float* Wxg        = (const float*)d_in[6];
    const float* Whg        = (const float*)d_in[7];
    const float* ag         = (const float*)d_in[8];
    const float* b1g        = (const float*)d_in[9];
    const float* b2g        = (const float*)d_in[10];
    const float* bg         = (const float*)d_in[11];
    const float* Wxc        = (const float*)d_in[12];
    const float* Whc        = (const float*)d_in[13];
    const float* ac         = (const float*)d_in[14];
    const float* b1c        = (const float*)d_in[15];
    const float* b2c        = (const float*)d_in[16];
    const float* bc         = (const float*)d_in[17];
    const float* softmax_w  = (const float*)d_in[18];
    const float* softmax_b  = (const float*)d_in[19];
    float* out = (float*)d_out;

    float *pXGC, *pO1;
    int* pidx;
    __nv_bfloat16 *pAb, *pEb, *pWbTw, *pWbT0;
    cudaGetSymbolAddress((void**)&pXGC, g_XGC);
    cudaGetSymbolAddress((void**)&pO1,  g_O1);
    cudaGetSymbolAddress((void**)&pidx, g_rowidx);
    cudaGetSymbolAddress((void**)&pAb,  g_Ab);
    cudaGetSymbolAddress((void**)&pEb,  g_Eb);
    cudaGetSymbolAddress((void**)&pWbTw, g_WbTw);
    cudaGetSymbolAddress((void**)&pWbT0, g_WbT0);

    cudaFuncSetAttribute(k_wave,
                         cudaFuncAttributeMaxDynamicSharedMemorySize, 218240);

    // launch 0: setup + embedding->bf16 + weight transposes (win + layer-0 Wx)
    k_convW<<<128 + 16384 + 1024 + 3072, 256>>>(
        input_data, out, out_size, embedding, win, Wxg, Wxc);

    // launch 1: X(bf16) = gather(Eb) @ win + bin_   -> g_Ab
    k_mgemm<true, true, true><<<dim3(HD / 128, TB / 128), 256>>>(
        pEb, pWbTw, bin_, nullptr, pAb, HD, pidx);

    // launch 2: XGC0 = Ab @ [Wxg0|Wxc0]
    k_mgemm<false, false, false><<<dim3(NG / 128, TB / 128), 256>>>(
        pAb, pWbT0, nullptr, pXGC, nullptr, NG, nullptr);

    // launch 3: 2-layer wavefront recurrence (257 steps)
    k_wave<<<128, 256, 218240>>>(
        Whg, Whc, Wxg, Wxc, pXGC,
        ag, b1g, b2g, bg, ac, b1c, b2c, bc, pO1);

    // NCE
    k_gather_samp<<<SD, 256>>>(nce, softmax_w, softmax_b);
    k_nce_true<<<TB / 8, 256>>>(targets, softmax_w, softmax_b, out);
    k_nce_samp<<<TB / 128, 256>>>(out);
}

// round 15
// speedup vs baseline: 1.0273x; 1.0273x over previous
#include <cuda_runtime.h>
#include <cuda_bf16.h>
#include <stdint.h>
#include <math.h>

// Problem constants
#define VD 16384
#define ED 1024
#define HD 1024
#define H2 2048
#define LD 2
#define BD 128
#define TD 256
#define SD 64
#define TB 32768   // B*T
#define NG 3072    // fused gate+cand projection width

// ---------------- scratch (__device__ globals; no allocations allowed) -------------
__device__ float g_XGC[(size_t)TB * NG];   // [T,B,3072]: 0..2047 gate, 2048.. cand
__device__ float g_O1 [(size_t)TB * HD];   // layer-1 fp32 outputs (NCE input)
__device__ __nv_bfloat16 g_O0b[(size_t)TB * HD];  // layer-0 bf16 outputs (layer-1 A operand)
__device__ float g_h [BD * HD];
__device__ __nv_bfloat16 g_hb [BD * HD];
__device__ __nv_bfloat16 g_RHb[BD * HD];
__device__ float g_sampWT[HD * SD];
__device__ float g_sampB [SD];
__device__ int   g_rowidx[TB];
__device__ unsigned g_barcnt;

__device__ __nv_bfloat16 g_Ab  [(size_t)TB * HD];  // X in bf16 (layer-0 A operand)
__device__ __nv_bfloat16 g_Eb  [(size_t)VD * ED];
__device__ __nv_bfloat16 g_WbTw[(size_t)HD * HD];  // win^T bf16
__device__ __nv_bfloat16 g_WbT0[(size_t)NG * HD];  // [Wxg0|Wxc0]^T bf16
__device__ __nv_bfloat16 g_WbT1[(size_t)NG * HD];  // [Wxg1|Wxc1]^T bf16

__device__ __forceinline__ float softplusf(float x) {
    return fmaxf(x, 0.f) + log1pf(expf(-fabsf(x)));
}

// ---------------- PTX helpers ----------------
__device__ __forceinline__ uint32_t s2u(const void* p) {
    uint32_t a;
    asm("{ .reg .u64 t; cvta.to.shared.u64 t, %1; cvt.u32.u64 %0, t; }" : "=r"(a) : "l"(p));
    return a;
}
__device__ __forceinline__ void cp16(uint32_t dst, const void* src) {
    asm volatile("cp.async.cg.shared.global [%0], [%1], 16;" :: "r"(dst), "l"(src));
}
#define CP_COMMIT() asm volatile("cp.async.commit_group;" ::: "memory")
#define CP_WAIT(n)  asm volatile("cp.async.wait_group %0;" :: "n"(n) : "memory")

__device__ __forceinline__ void ldmatrix_x4(uint32_t& r0, uint32_t& r1,
                                            uint32_t& r2, uint32_t& r3, uint32_t addr) {
    asm volatile("ldmatrix.sync.aligned.m8n8.x4.shared.b16 {%0,%1,%2,%3}, [%4];"
                 : "=r"(r0), "=r"(r1), "=r"(r2), "=r"(r3) : "r"(addr));
}
__device__ __forceinline__ void ldmatrix_x2(uint32_t& r0, uint32_t& r1, uint32_t addr) {
    asm volatile("ldmatrix.sync.aligned.m8n8.x2.shared.b16 {%0,%1}, [%2];"
                 : "=r"(r0), "=r"(r1) : "r"(addr));
}
__device__ __forceinline__ void mma16816(float* d, const uint32_t* a, const uint32_t* b) {
    asm volatile("mma.sync.aligned.m16n8k16.row.col.f32.bf16.bf16.f32 "
                 "{%0,%1,%2,%3},{%4,%5,%6,%7},{%8,%9},{%0,%1,%2,%3};"
                 : "+f"(d[0]), "+f"(d[1]), "+f"(d[2]), "+f"(d[3])
                 : "r"(a[0]), "r"(a[1]), "r"(a[2]), "r"(a[3]), "r"(b[0]), "r"(b[1]));
}

// single-counter software grid barrier (round-12 proven form; DO NOT CHANGE)
__device__ __forceinline__ void gsync(unsigned target) {
    __syncthreads();
    if (threadIdx.x == 0) {
        __threadfence();
        atomicAdd(&g_barcnt, 1u);
        while (*(volatile unsigned*)&g_barcnt < target) __nanosleep(16);
        __threadfence();
    }
    __syncthreads();
}

// ---------------- upfront fused kernel: setup + emb->bf16 + ALL weight transposes ---
__global__ void k_convW(const int* __restrict__ input_data, float* out, int out_size,
                        const float* __restrict__ emb, const float* __restrict__ win,
                        const float* __restrict__ Wxg, const float* __restrict__ Wxc)
{
    const int bx = blockIdx.x;
    const int tid = threadIdx.x;
    if (bx < 128) {
        if (bx == 0 && tid == 0) {
            g_barcnt = 0u;
            for (int i = 0; i < out_size; i++) out[i] = 0.f;
        }
        int r = bx * 256 + tid;
        int t = r >> 7, b = r & 127;
        g_rowidx[r] = input_data[b * TD + t];
    } else if (bx < 128 + 16384) {
        int i = (bx - 128) * 256 + tid;
        float4 v = ((const float4*)emb)[i];
        __nv_bfloat162* o = (__nv_bfloat162*)g_Eb;
        o[2 * i + 0] = __floats2bfloat162_rn(v.x, v.y);
        o[2 * i + 1] = __floats2bfloat162_rn(v.z, v.w);
    } else {
        __shared__ float tile[32][33];
        const int tx = tid & 31, ty = tid >> 5;   // 32 x 8
        if (bx < 128 + 16384 + 1024) {
            int idx = bx - (128 + 16384);
            int n0 = (idx & 31) * 32, k0 = (idx >> 5) * 32;
            #pragma unroll
            for (int j = 0; j < 4; j++)
                tile[ty + 8 * j][tx] = win[(size_t)(k0 + ty + 8 * j) * HD + n0 + tx];
            __syncthreads();
            #pragma unroll
            for (int j = 0; j < 4; j++)
                g_WbTw[(size_t)(n0 + ty + 8 * j) * HD + k0 + tx] =
                    __float2bfloat16(tile[tx][ty + 8 * j]);
        } else {
            int idx = bx - (128 + 16384 + 1024);
            int l = idx / 3072;
            idx -= l * 3072;
            const float* Wg = Wxg + (size_t)l * HD * H2;
            const float* Wc = Wxc + (size_t)l * HD * HD;
            __nv_bfloat16* dst = l ? g_WbT1 : g_WbT0;
            int n0 = (idx % 96) * 32, k0 = (idx / 96) * 32;
            #pragma unroll
            for (int j = 0; j < 4; j++) {
                int k = k0 + ty + 8 * j;
                int n = n0 + tx;
                tile[ty + 8 * j][tx] = (n < 2048) ? Wg[(size_t)k * H2 + n]
                                                  : Wc[(size_t)k * HD + (n - 2048)];
            }
            __syncthreads();
            #pragma unroll
            for (int j = 0; j < 4; j++)
                dst[(size_t)(n0 + ty + 8 * j) * HD + k0 + tx] =
                    __float2bfloat16(tile[tx][ty + 8 * j]);
        }
    }
}

__global__ void k_gather_samp(const int* __restrict__ nce,
                              const float* __restrict__ sw,
                              const float* __restrict__ sb) {
    int s = blockIdx.x;
    int row = nce[s];
    const float* src = sw + (size_t)row * HD;
    for (int k = threadIdx.x; k < HD; k += blockDim.x)
        g_sampWT[k * SD + s] = src[k];
    if (threadIdx.x == 0) g_sampB[s] = sb[row];
}

// ---------------- bf16 mma.sync GEMM (fp32 or bf16 output) ----------------
#define LDP 40

template<bool GATHER, bool BIAS, bool OB16>
__global__ __launch_bounds__(256)
void k_mgemm(const __nv_bfloat16* __restrict__ A, const __nv_bfloat16* __restrict__ BT,
             const float* __restrict__ bias, float* __restrict__ Cf,
             __nv_bfloat16* __restrict__ Cb, int N, const int* __restrict__ gidx)
{
    __shared__ __align__(16) __nv_bfloat16 sA[2][128 * LDP];
    __shared__ __align__(16) __nv_bfloat16 sB[2][128 * LDP];

    const int tid = threadIdx.x;
    const int rowBase = blockIdx.y * 128;
    const int colBase = blockIdx.x * 128;

    const int lrow = tid & 127;
    const bool isB = tid >= 128;
    const __nv_bfloat16* src;
    if (isB) {
        src = BT + (size_t)(colBase + lrow) * 1024;
    } else {
        size_t ar = GATHER ? (size_t)gidx[rowBase + lrow] : (size_t)(rowBase + lrow);
        src = A + ar * 1024;
    }
    uint32_t dst0 = s2u(isB ? (const void*)&sB[0][lrow * LDP] : (const void*)&sA[0][lrow * LDP]);
    uint32_t dst1 = s2u(isB ? (const void*)&sB[1][lrow * LDP] : (const void*)&sA[1][lrow * LDP]);

    const int wid = tid >> 5, lane = tid & 31;
    const int mb = (wid & 1) * 64;
    const int nb = (wid >> 1) * 32;
    const int arow_l = (lane & 7) + ((lane >> 3) & 1) * 8;
    const int acol_l = (lane >> 4) * 8;
    const int brow_l = (lane & 7) + (lane >> 4) * 8;
    const int bcol_l = ((lane >> 3) & 1) * 8;
    const uint32_t aS0 = s2u(sA[0]), aS1 = s2u(sA[1]);
    const uint32_t bS0 = s2u(sB[0]), bS1 = s2u(sB[1]);

    float acc[4][4][4];
    #pragma unroll
    for (int mt = 0; mt < 4; mt++)
        #pragma unroll
        for (int nt = 0; nt < 4; nt++)
            #pragma unroll
            for (int q = 0; q < 4; q++) acc[mt][nt][q] = 0.f;

    const int S = 32;
    {
        const __nv_bfloat16* p = src;
        #pragma unroll
        for (int c = 0; c < 4; c++) cp16(dst0 + c * 16, p + c * 8);
        CP_COMMIT();
    }

    for (int s = 0; s < S; s++) {
        if (s + 1 < S) {
            uint32_t d = ((s + 1) & 1) ? dst1 : dst0;
            const __nv_bfloat16* p = src + (s + 1) * 32;
            #pragma unroll
            for (int c = 0; c < 4; c++) cp16(d + c * 16, p + c * 8);
            CP_COMMIT();
            CP_WAIT(1);
        } else {
            CP_WAIT(0);
        }
        __syncthreads();

        const uint32_t aS = (s & 1) ? aS1 : aS0;
        const uint32_t bS = (s & 1) ? bS1 : bS0;
        #pragma unroll
        for (int kk = 0; kk < 32; kk += 16) {
            uint32_t af[4][4];
            #pragma unroll
            for (int mt = 0; mt < 4; mt++) {
                uint32_t ad = aS + (uint32_t)(((mb + mt * 16 + arow_l) * LDP) + kk + acol_l) * 2u;
                ldmatrix_x4(af[mt][0], af[mt][1], af[mt][2], af[mt][3], ad);
            }
            uint32_t bf[2][4];
            #pragma unroll
            for (int nt2 = 0; nt2 < 2; nt2++) {
                uint32_t bd = bS + (uint32_t)(((nb + nt2 * 16 + brow_l) * LDP) + kk + bcol_l) * 2u;
                ldmatrix_x4(bf[nt2][0], bf[nt2][1], bf[nt2][2], bf[nt2][3], bd);
            }
            #pragma unroll
            for (int mt = 0; mt < 4; mt++)
                #pragma unroll
                for (int nt = 0; nt < 4; nt++)
                    mma16816(acc[mt][nt], af[mt], &bf[nt >> 1][(nt & 1) * 2]);
        }
        __syncthreads();
    }

    const int erow = lane >> 2;
    const int ecol = (lane & 3) * 2;
    #pragma unroll
    for (int mt = 0; mt < 4; mt++) {
        #pragma unroll
        for (int nt = 0; nt < 4; nt++) {
            int r0 = rowBase + mb + mt * 16 + erow;
            int c0 = colBase + nb + nt * 8 + ecol;
            float b0 = 0.f, b1 = 0.f;
            if (BIAS) { b0 = bias[c0]; b1 = bias[c0 + 1]; }
            float v00 = acc[mt][nt][0] + b0, v01 = acc[mt][nt][1] + b1;
            float v10 = acc[mt][nt][2] + b0, v11 = acc[mt][nt][3] + b1;
            if (OB16) {
                __nv_bfloat162 p0 = __floats2bfloat162_rn(v00, v01);
                __nv_bfloat162 p1 = __floats2bfloat162_rn(v10, v11);
                *(__nv_bfloat162*)&Cb[(size_t)r0 * N + c0] = p0;
                *(__nv_bfloat162*)&Cb[(size_t)(r0 + 8) * N + c0] = p1;
            } else {
                *(float2*)&Cf[(size_t)r0 * N + c0] = make_float2(v00, v01);
                *(float2*)&Cf[(size_t)(r0 + 8) * N + c0] = make_float2(v10, v11);
            }
        }
    }
}

// ---------------- persistent per-layer MI-GRU recurrence (512 threads) --------------
// 128 CTAs x 512 threads (two warp groups). CTA c owns r-gate cols [8c,8c+8),
// u-gate cols [1024+8c,+8), cand cols [8c,+8). Group 0 (warps 0-7) processes
// K-chunks 0-3, group 1 (warps 8-15) chunks 4-7, concurrently; partials merged
// through an 8KB smem reduction. u stays in group-0 registers across the barrier.
// Pair-staged cp.async pipeline (depth 2). Two gsync barriers per step.
template<int OM>   // 0: bf16 output only (layer 0); 1: fp32 output only (layer 1)
__global__ __launch_bounds__(512)
void k_layerX(const float* __restrict__ Whg, const float* __restrict__ Whc,
              const float* __restrict__ XGC,
              const float* __restrict__ ag, const float* __restrict__ b1g,
              const float* __restrict__ b2g, const float* __restrict__ bg,
              const float* __restrict__ ac, const float* __restrict__ b1c,
              const float* __restrict__ b2c, const float* __restrict__ bcv,
              float* __restrict__ outF, __nv_bfloat16* __restrict__ outB,
              unsigned barBase)
{
    extern __shared__ char smRaw[];
    __nv_bfloat16* Wg  = (__nv_bfloat16*)smRaw;       // [16][1032] bf16 = 33024B
    __nv_bfloat16* Wc  = Wg + 16 * 1032;              // [8][1032]  = 16512B
    __nv_bfloat16* stg = Wc + 8 * 1032;               // 4 chunk buffers x 34816B
    float* red = (float*)stg;                         // reduction scratch (reuses stg)

    const int cta = blockIdx.x;
    const int tid = threadIdx.x;
    const int wid = tid >> 5, lane = tid & 31;
    const int grp = tid >> 8;          // warp group 0 or 1
    const int wid8 = wid & 7;          // warp within group
    const int tid8 = tid & 255;        // thread within group
    const int col0 = cta * 8;

    // weight slices -> SMEM: Wg rows 0-7 = r cols, rows 8-15 = u cols
    for (int i = tid; i < 16 * 1024; i += 512) {
        int n = i & 15, k = i >> 4;
        int col = (n < 8) ? (col0 + n) : (1024 + col0 + (n - 8));
        Wg[n * 1032 + k] = __float2bfloat16(Whg[(size_t)k * H2 + col]);
    }
    for (int i = tid; i < 8 * 1024; i += 512) {
        int n = i & 7, k = i >> 3;
        Wc[n * 1032 + k] = __float2bfloat16(Whc[(size_t)k * HD + col0 + n]);
    }

    const int arow_l = (lane & 7) + ((lane >> 3) & 1) * 8;
    const int acol_l = (lane >> 4) * 8;
    const int brow_l = (lane & 7) + (lane >> 4) * 8;
    const int bcol_l = ((lane >> 3) & 1) * 8;
    const int l16 = lane & 15;

    const uint32_t stB = s2u(stg);
    const uint32_t wgB = s2u(Wg);
    const uint32_t wcB = s2u(Wc);

    const int erow = lane >> 2;
    const int ecol = (lane & 3) * 2;
    const int r0 = wid8 * 16 + erow;

    float agr[2], b1r[2], b2r[2], bgr[2];
    float agu[2], b1u[2], b2u[2], bgu[2];
    float acv[2], b1cv[2], b2cv[2], bcvv[2];
    #pragma unroll
    for (int j = 0; j < 2; j++) {
        int cr = col0 + ecol + j;
        int cu = 1024 + cr;
        agr[j] = ag[cr]; b1r[j] = b1g[cr]; b2r[j] = b2g[cr]; bgr[j] = bg[cr];
        agu[j] = ag[cu]; b1u[j] = b1g[cu]; b2u[j] = b2g[cu]; bgu[j] = bg[cu];
        acv[j] = ac[cr]; b1cv[j] = b1c[cr]; b2cv[j] = b2c[cr]; bcvv[j] = bcv[cr];
    }

    // loader mapping: 512 threads, 4 threads/row, 4x16B each per chunk buffer
    const int srow = tid & 127;
    const int scb  = (tid >> 7) & 3;                // 0..3
    const uint32_t sdst_off = (uint32_t)(srow * 272 + scb * 64);
    const int ssrc_off = scb * 32;                  // bf16 elements within 128-col chunk

    {
        float4 z = make_float4(0.f, 0.f, 0.f, 0.f);
        if (tid < 256) {
            __stcg((float4*)(g_h + cta * 1024 + tid * 4), z);
            uint2 zb = make_uint2(0u, 0u);
            __stcg((uint2*)(g_hb + cta * 1024 + tid * 4), zb);
        }
    }
    unsigned bar = barBase + 1;
    gsync(bar);

    for (int t = 0; t < TD; t++) {
        const float* Xt = XGC + (size_t)t * BD * NG;
        float ur[2][2];
        float2 hvp[2];

        // ================= gate phase =================
        {
            float2 gxr[2], gxu[2];
            #pragma unroll
            for (int half = 0; half < 2; half++) {
                int row = r0 + half * 8;
                gxr[half] = __ldcg((const float2*)(Xt + (size_t)row * NG + col0 + ecol));
                gxu[half] = __ldcg((const float2*)(Xt + (size_t)row * NG + 1024 + col0 + ecol));
                hvp[half] = __ldcg((const float2*)(g_h + (size_t)row * 1024 + col0 + ecol));
            }

            float acc[2][4];
            #pragma unroll
            for (int nt = 0; nt < 2; nt++)
                #pragma unroll
                for (int q = 0; q < 4; q++) acc[nt][q] = 0.f;

            // prologue: pair 0 (g0 chunk 0 -> buf0, g1 chunk 4 -> buf2)
            {
                const __nv_bfloat16* s0 = g_hb + (size_t)srow * 1024 + 0 * 128 + ssrc_off;
                const __nv_bfloat16* s1 = g_hb + (size_t)srow * 1024 + 4 * 128 + ssrc_off;
                uint32_t d0 = stB + 0u * 34816u + sdst_off;
                uint32_t d1 = stB + 2u * 34816u + sdst_off;
                #pragma unroll
                for (int c = 0; c < 4; c++) { cp16(d0 + c * 16, s0 + c * 8);
                                              cp16(d1 + c * 16, s1 + c * 8); }
                CP_COMMIT();
            }
            for (int i = 0; i < 4; i++) {
                if (i + 1 < 4) {
                    const __nv_bfloat16* s0 = g_hb + (size_t)srow * 1024 + (i + 1) * 128 + ssrc_off;
                    const __nv_bfloat16* s1 = g_hb + (size_t)srow * 1024 + (i + 5) * 128 + ssrc_off;
                    uint32_t d0 = stB + (uint32_t)((i + 1) & 1) * 34816u + sdst_off;
                    uint32_t d1 = stB + (uint32_t)(2 + ((i + 1) & 1)) * 34816u + sdst_off;
                    #pragma unroll
                    for (int c = 0; c < 4; c++) { cp16(d0 + c * 16, s0 + c * 8);
                                                  cp16(d1 + c * 16, s1 + c * 8); }
                    CP_COMMIT();
                    CP_WAIT(1);
                } else {
                    CP_WAIT(0);
                }
                __syncthreads();
                uint32_t aB = stB + (uint32_t)(grp * 2 + (i & 1)) * 34816u;
                int kg0 = (grp * 4 + i) * 128;
                #pragma unroll
                for (int ks = 0; ks < 8; ks++) {
                    int kloc = ks * 16;
                    uint32_t af[4];
                    ldmatrix_x4(af[0], af[1], af[2], af[3],
                        aB + (uint32_t)((wid8 * 16 + arow_l) * 272 + (kloc + acol_l) * 2));
                    uint32_t bf[4];
                    ldmatrix_x4(bf[0], bf[1], bf[2], bf[3],
                        wgB + (uint32_t)(brow_l * 2064 + (kg0 + kloc + bcol_l) * 2));
                    mma16816(acc[0], af, &bf[0]);
                    mma16816(acc[1], af, &bf[2]);
                }
                __syncthreads();
            }

            // merge group-1 partials into group-0
            if (grp == 1) {
                #pragma unroll
                for (int nt = 0; nt < 2; nt++)
                    #pragma unroll
                    for (int q = 0; q < 4; q++)
                        red[tid8 * 8 + nt * 4 + q] = acc[nt][q];
            }
            __syncthreads();
            if (grp == 0) {
                #pragma unroll
                for (int nt = 0; nt < 2; nt++)
                    #pragma unroll
                    for (int q = 0; q < 4; q++)
                        acc[nt][q] += red[tid8 * 8 + nt * 4 + q];

                #pragma unroll
                for (int half = 0; half < 2; half++) {
                    int row = r0 + half * 8;
                    float gh0 = acc[0][half * 2 + 0], gh1 = acc[0][half * 2 + 1];
                    float z0 = agr[0] * gxr[half].x * gh0 + b1r[0] * gxr[half].x + b2r[0] * gh0 + bgr[0];
                    float z1 = agr[1] * gxr[half].y * gh1 + b1r[1] * gxr[half].y + b2r[1] * gh1 + bgr[1];
                    float s0 = 1.f / (1.f + expf(-z0));
                    float s1 = 1.f / (1.f + expf(-z1));
                    __nv_bfloat162 p = __floats2bfloat162_rn(s0 * hvp[half].x, s1 * hvp[half].y);
                    __stcg((uint32_t*)(g_RHb + (size_t)row * 1024 + col0 + ecol), *(uint32_t*)&p);

                    float uh0 = acc[1][half * 2 + 0], uh1 = acc[1][half * 2 + 1];
                    float y0 = agu[0] * gxu[half].x * uh0 + b1u[0] * gxu[half].x + b2u[0] * uh0 + bgu[0];
                    float y1 = agu[1] * gxu[half].y * uh1 + b1u[1] * gxu[half].y + b2u[1] * uh1 + bgu[1];
                    ur[half][0] = 1.f / (1.f + expf(-y0));
                    ur[half][1] = 1.f / (1.f + expf(-y1));
                }
            }
        }
        bar++; gsync(bar);

        // ================= cand phase =================
        {
            float2 cxv[2];
            #pragma unroll
            for (int half = 0; half < 2; half++) {
                int row = r0 + half * 8;
                cxv[half] = __ldcg((const float2*)(Xt + (size_t)row * NG + 2048 + col0 + ecol));
            }

            float acc[4] = {0.f, 0.f, 0.f, 0.f};
            {
                const __nv_bfloat16* s0 = g_RHb + (size_t)srow * 1024 + 0 * 128 + ssrc_off;
                const __nv_bfloat16* s1 = g_RHb + (size_t)srow * 1024 + 4 * 128 + ssrc_off;
                uint32_t d0 = stB + 0u * 34816u + sdst_off;
                uint32_t d1 = stB + 2u * 34816u + sdst_off;
                #pragma unroll
                for (int c = 0; c < 4; c++) { cp16(d0 + c * 16, s0 + c * 8);
                                              cp16(d1 + c * 16, s1 + c * 8); }
                CP_COMMIT();
            }
            for (int i = 0; i < 4; i++) {
                if (i + 1 < 4) {
                    const __nv_bfloat16* s0 = g_RHb + (size_t)srow * 1024 + (i + 1) * 128 + ssrc_off;
                    const __nv_bfloat16* s1 = g_RHb + (size_t)srow * 1024 + (i + 5) * 128 + ssrc_off;
                    uint32_t d0 = stB + (uint32_t)((i + 1) & 1) * 34816u + sdst_off;
                    uint32_t d1 = stB + (uint32_t)(2 + ((i + 1) & 1)) * 34816u + sdst_off;
                    #pragma unroll
                    for (int c = 0; c < 4; c++) { cp16(d0 + c * 16, s0 + c * 8);
                                                  cp16(d1 + c * 16, s1 + c * 8); }
                    CP_COMMIT();
                    CP_WAIT(1);
                } else {
                    CP_WAIT(0);
                }
                __syncthreads();
                uint32_t aB = stB + (uint32_t)(grp * 2 + (i & 1)) * 34816u;
                int kg0 = (grp * 4 + i) * 128;
                #pragma unroll
                for (int ks = 0; ks < 8; ks++) {
                    int kloc = ks * 16;
                    uint32_t af[4];
                    ldmatrix_x4(af[0], af[1], af[2], af[3],
                        aB + (uint32_t)((wid8 * 16 + arow_l) * 272 + (kloc + acol_l) * 2));
                    uint32_t bf2[2];
                    ldmatrix_x2(bf2[0], bf2[1],
                        wcB + (uint32_t)((l16 & 7) * 2064 + (kg0 + kloc + (l16 >> 3) * 8) * 2));
                    mma16816(acc, af, bf2);
                }
                __syncthreads();
            }

            if (grp == 1) {
                #pragma unroll
                for (int q = 0; q < 4; q++)
                    red[tid8 * 4 + q] = acc[q];
            }
            __syncthreads();
            if (grp == 0) {
                #pragma unroll
                for (int q = 0; q < 4; q++)
                    acc[q] += red[tid8 * 4 + q];

                #pragma unroll
                for (int half = 0; half < 2; half++) {
                    int row = r0 + half * 8;
                    float ch0 = acc[half * 2 + 0], ch1 = acc[half * 2 + 1];
                    float z0 = acv[0] * cxv[half].x * ch0 + b1cv[0] * cxv[half].x + b2cv[0] * ch0 + bcvv[0];
                    float z1 = acv[1] * cxv[half].y * ch1 + b1cv[1] * cxv[half].y + b2cv[1] * ch1 + bcvv[1];
                    float c0 = tanhf(z0), c1 = tanhf(z1);
                    float hn0 = ur[half][0] * hvp[half].x + (1.f - ur[half][0]) * c0;
                    float hn1 = ur[half][1] * hvp[half].y + (1.f - ur[half][1]) * c1;
                    __stcg((float2*)(g_h + (size_t)row * 1024 + col0 + ecol), make_float2(hn0, hn1));
                    __nv_bfloat162 p = __floats2bfloat162_rn(hn0, hn1);
                    __stcg((uint32_t*)(g_hb + (size_t)row * 1024 + col0 + ecol), *(uint32_t*)&p);
                    size_t off = (size_t)t * BD * HD + (size_t)row * HD + col0 + ecol;
                    if (OM == 0)
                        *(__nv_bfloat162*)(outB + off) = p;
                    else
                        *(float2*)(outF + off) = make_float2(hn0, hn1);
                }
            }
        }
        bar++; gsync(bar);
    }
}

// ---------------- NCE ----------------
__global__ __launch_bounds__(256)
void k_nce_samp(float* __restrict__ outsum)
{
    __shared__ float As[8][132];
    __shared__ float Bs[8][64];
    __shared__ float red[256];
    const int tid = threadIdx.x;
    const int rowBase = blockIdx.x * 128;

    const int arow = tid >> 1;
    const int acol = (tid & 1) << 2;
    int gi = rowBase + arow;
    size_t aoff = (size_t)((gi & 255) * BD + (gi >> 8)) * HD;

    const int brow = tid >> 5;
    const int bcl  = (tid & 31) << 1;
    const int ty = tid >> 4;
    const int tx = tid & 15;

    float acc[8][4];
    #pragma unroll
    for (int i = 0; i < 8; i++)
        #pragma unroll
        for (int j = 0; j < 4; j++) acc[i][j] = 0.f;

    for (int k0 = 0; k0 < HD; k0 += 8) {
        float4 av = *(const float4*)(g_O1 + aoff + k0 + acol);
        As[acol + 0][arow] = av.x;
        As[acol + 1][arow] = av.y;
        As[acol + 2][arow] = av.z;
        As[acol + 3][arow] = av.w;
        float2 bw = *(const float2*)(g_sampWT + (size_t)(k0 + brow) * SD + bcl);
        Bs[brow][bcl]     = bw.x;
        Bs[brow][bcl + 1] = bw.y;
        __syncthreads();
        #pragma unroll
        for (int k = 0; k < 8; k++) {
            float ar[8], br[4];
            *(float4*)&ar[0] = *(const float4*)&As[k][ty * 8];
            *(float4*)&ar[4] = *(const float4*)&As[k][ty * 8 + 4];
            *(float4*)&br[0] = *(const float4*)&Bs[k][tx * 4];
            #pragma unroll
            for (int i = 0; i < 8; i++)
                #pragma unroll
                for (int j = 0; j < 4; j++)
                    acc[i][j] += ar[i] * br[j];
        }
        __syncthreads();
    }

    float s = 0.f;
    #pragma unroll
    for (int j = 0; j < 4; j++) {
        float sbv = g_sampB[tx * 4 + j];
        #pragma unroll
        for (int i = 0; i < 8; i++)
            s += softplusf(acc[i][j] + sbv);
    }
    red[tid] = s;
    __syncthreads();
    for (int o = 128; o > 0; o >>= 1) {
        if (tid < o) red[tid] += red[tid + o];
        __syncthreads();
    }
    if (tid == 0) atomicAdd(outsum, red[0] * (1.f / 32768.f));
}

__global__ __launch_bounds__(256)
void k_nce_true(const int* __restrict__ targets, const float* __restrict__ sw,
                const float* __restrict__ sb, float* __restrict__ outsum)
{
    __shared__ float red[8];
    const int warp = threadIdx.x >> 5;
    const int lane = threadIdx.x & 31;
    const int i = blockIdx.x * 8 + warp;
    const int label = targets[i];
    const float* orow = g_O1 + (size_t)((i & 255) * BD + (i >> 8)) * HD;
    const float* wrow = sw + (size_t)label * HD;

    float s = 0.f;
    #pragma unroll
    for (int k0 = 0; k0 < HD; k0 += 128) {
        float4 a = *(const float4*)(orow + k0 + lane * 4);
        float4 w = *(const float4*)(wrow + k0 + lane * 4);
        s += a.x * w.x + a.y * w.y + a.z * w.z + a.w * w.w;
    }
    #pragma unroll
    for (int o = 16; o > 0; o >>= 1) s += __shfl_xor_sync(0xffffffffu, s, o);
    if (lane == 0) {
        float logit = s + sb[label];
        red[warp] = softplusf(-logit);
    }
    __syncthreads();
    if (threadIdx.x == 0) {
        float t = 0.f;
        #pragma unroll
        for (int w = 0; w < 8; w++) t += red[w];
        atomicAdd(outsum, t * (1.f / 32768.f));
    }
}

// ---------------- launch ----------------
extern "C" void kernel_launch(void* const* d_in, const int* in_sizes, int n_in,
                              void* d_out, int out_size)
{
    const int*   input_data = (const int*)  d_in[0];
    const int*   targets    = (const int*)  d_in[1];
    const int*   nce        = (const int*)  d_in[2];
    const float* embedding  = (const float*)d_in[3];
    const float* win        = (const float*)d_in[4];
    const float* bin_       = (const float*)d_in[5];
    const float* Wxg        = (const float*)d_in[6];
    const float* Whg        = (const float*)d_in[7];
    const float* ag         = (const float*)d_in[8];
    const float* b1g        = (const float*)d_in[9];
    const float* b2g        = (const float*)d_in[10];
    const float* bg         = (const float*)d_in[11];
    const float* Wxc        = (const float*)d_in[12];
    const float* Whc        = (const float*)d_in[13];
    const float* ac         = (const float*)d_in[14];
    const float* b1c        = (const float*)d_in[15];
    const float* b2c        = (const float*)d_in[16];
    const float* bc         = (const float*)d_in[17];
    const float* softmax_w  = (const float*)d_in[18];
    const float* softmax_b  = (const float*)d_in[19];
    float* out = (float*)d_out;

    float *pXGC, *pO1;
    int* pidx;
    __nv_bfloat16 *pAb, *pEb, *pWbTw, *pWbT0, *pWbT1, *pO0b;
    cudaGetSymbolAddress((void**)&pXGC, g_XGC);
    cudaGetSymbolAddress((void**)&pO1,  g_O1);
    cudaGetSymbolAddress((void**)&pO0b, g_O0b);
    cudaGetSymbolAddress((void**)&pidx, g_rowidx);
    cudaGetSymbolAddress((void**)&pAb,  g_Ab);
    cudaGetSymbolAddress((void**)&pEb,  g_Eb);
    cudaGetSymbolAddress((void**)&pWbTw, g_WbTw);
    cudaGetSymbolAddress((void**)&pWbT0, g_WbT0);
    cudaGetSymbolAddress((void**)&pWbT1, g_WbT1);

    cudaFuncSetAttribute(k_layerX<0>,
                         cudaFuncAttributeMaxDynamicSharedMemorySize, 188800);
    cudaFuncSetAttribute(k_layerX<1>,
                         cudaFuncAttributeMaxDynamicSharedMemorySize, 188800);

    // launch 0: setup + embedding->bf16 + all weight transposes
    k_convW<<<128 + 16384 + 1024 + 3072 + 3072, 256>>>(
        input_data, out, out_size, embedding, win, Wxg, Wxc);

    // launch 1: X(bf16) = gather(Eb) @ win + bin_   -> g_Ab directly
    k_mgemm<true, true, true><<<dim3(HD / 128, TB / 128), 256>>>(
        pEb, pWbTw, bin_, nullptr, pAb, HD, pidx);

    // launch 2: XGC = Ab @ [Wxg0|Wxc0]
    k_mgemm<false, false, false><<<dim3(NG / 128, TB / 128), 256>>>(
        pAb, pWbT0, nullptr, pXGC, nullptr, NG, nullptr);

    // launch 3: layer-0 recurrence (bf16 output only)
    k_layerX<0><<<128, 512, 188800>>>(
        Whg, Whc, pXGC,
        ag, b1g, b2g, bg, ac, b1c, b2c, bc,
        nullptr, pO0b, 0u);

    // launch 4: XGC = O0b @ [Wxg1|Wxc1]
    k_mgemm<false, false, false><<<dim3(NG / 128, TB / 128), 256>>>(
        pO0b, pWbT1, nullptr, pXGC, nullptr, NG, nullptr);

    // launch 5: layer-1 recurrence (fp32 output only)
    k_layerX<1><<<128, 512, 188800>>>(
        Whg + (size_t)HD * H2, Whc + (size_t)HD * HD, pXGC,
        ag + H2, b1g + H2, b2g + H2, bg + H2,
        ac + HD, b1c + HD, b2c + HD, bc + HD,
        pO1, nullptr, 1u + 2u * TD);

    // NCE
    k_gather_samp<<<SD, 256>>>(nce, softmax_w, softmax_b);
    k_nce_true<<<TB / 8, 256>>>(targets, softmax_w, softmax_b, out);
    k_nce_samp<<<TB / 128, 256>>>(out);
}

// round 16
// speedup vs baseline: 1.0728x; 1.0443x over previous
#include <cuda_runtime.h>
#include <cuda_bf16.h>
#include <stdint.h>
#include <math.h>

// Problem constants
#define VD 16384
#define ED 1024
#define HD 1024
#define H2 2048
#define LD 2
#define BD 128
#define TD 256
#define SD 64
#define TB 32768   // B*T
#define NG 3072    // fused gate+cand projection width

// ---------------- scratch (__device__ globals; no allocations allowed) -------------
__device__ float g_XGC[(size_t)TB * NG];   // [T,B,3072]: 0..2047 gate, 2048.. cand
__device__ float g_O1 [(size_t)TB * HD];   // layer-1 fp32 outputs (NCE input)
__device__ __nv_bfloat16 g_O0b[(size_t)TB * HD];  // layer-0 bf16 outputs (layer-1 A operand)
__device__ float g_h [BD * HD];
__device__ __nv_bfloat16 g_hb [BD * HD];
__device__ __nv_bfloat16 g_RHb[BD * HD];
__device__ float g_sampWT[HD * SD];
__device__ float g_sampB [SD];
__device__ int   g_rowidx[TB];
__device__ unsigned g_barcnt;

__device__ __nv_bfloat16 g_Ab  [(size_t)TB * HD];  // X in bf16 (layer-0 A operand)
__device__ __nv_bfloat16 g_Eb  [(size_t)VD * ED];
__device__ __nv_bfloat16 g_WbTw[(size_t)HD * HD];  // win^T bf16
__device__ __nv_bfloat16 g_WbT0[(size_t)NG * HD];  // [Wxg0|Wxc0]^T bf16
__device__ __nv_bfloat16 g_WbT1[(size_t)NG * HD];  // [Wxg1|Wxc1]^T bf16

__device__ __forceinline__ float softplusf(float x) {
    return fmaxf(x, 0.f) + log1pf(expf(-fabsf(x)));
}

// ---------------- PTX helpers ----------------
__device__ __forceinline__ uint32_t s2u(const void* p) {
    uint32_t a;
    asm("{ .reg .u64 t; cvta.to.shared.u64 t, %1; cvt.u32.u64 %0, t; }" : "=r"(a) : "l"(p));
    return a;
}
__device__ __forceinline__ void cp16(uint32_t dst, const void* src) {
    asm volatile("cp.async.cg.shared.global [%0], [%1], 16;" :: "r"(dst), "l"(src));
}
#define CP_COMMIT() asm volatile("cp.async.commit_group;" ::: "memory")
#define CP_WAIT(n)  asm volatile("cp.async.wait_group %0;" :: "n"(n) : "memory")

__device__ __forceinline__ void ldmatrix_x4(uint32_t& r0, uint32_t& r1,
                                            uint32_t& r2, uint32_t& r3, uint32_t addr) {
    asm volatile("ldmatrix.sync.aligned.m8n8.x4.shared.b16 {%0,%1,%2,%3}, [%4];"
                 : "=r"(r0), "=r"(r1), "=r"(r2), "=r"(r3) : "r"(addr));
}
__device__ __forceinline__ void ldmatrix_x2(uint32_t& r0, uint32_t& r1, uint32_t addr) {
    asm volatile("ldmatrix.sync.aligned.m8n8.x2.shared.b16 {%0,%1}, [%2];"
                 : "=r"(r0), "=r"(r1) : "r"(addr));
}
__device__ __forceinline__ void mma16816(float* d, const uint32_t* a, const uint32_t* b) {
    asm volatile("mma.sync.aligned.m16n8k16.row.col.f32.bf16.bf16.f32 "
                 "{%0,%1,%2,%3},{%4,%5,%6,%7},{%8,%9},{%0,%1,%2,%3};"
                 : "+f"(d[0]), "+f"(d[1]), "+f"(d[2]), "+f"(d[3])
                 : "r"(a[0]), "r"(a[1]), "r"(a[2]), "r"(a[3]), "r"(b[0]), "r"(b[1]));
}

// single-counter software grid barrier (round-12 proven form; DO NOT CHANGE)
__device__ __forceinline__ void gsync(unsigned target) {
    __syncthreads();
    if (threadIdx.x == 0) {
        __threadfence();
        atomicAdd(&g_barcnt, 1u);
        while (*(volatile unsigned*)&g_barcnt < target) __nanosleep(16);
        __threadfence();
    }
    __syncthreads();
}

// ---------------- upfront fused kernel: setup + emb->bf16 + ALL weight transposes ---
__global__ void k_convW(const int* __restrict__ input_data, float* out, int out_size,
                        const float* __restrict__ emb, const float* __restrict__ win,
                        const float* __restrict__ Wxg, const float* __restrict__ Wxc)
{
    const int bx = blockIdx.x;
    const int tid = threadIdx.x;
    if (bx < 128) {
        if (bx == 0 && tid == 0) {
            g_barcnt = 0u;
            for (int i = 0; i < out_size; i++) out[i] = 0.f;
        }
        int r = bx * 256 + tid;
        int t = r >> 7, b = r & 127;
        g_rowidx[r] = input_data[b * TD + t];
    } else if (bx < 128 + 16384) {
        int i = (bx - 128) * 256 + tid;
        float4 v = ((const float4*)emb)[i];
        __nv_bfloat162* o = (__nv_bfloat162*)g_Eb;
        o[2 * i + 0] = __floats2bfloat162_rn(v.x, v.y);
        o[2 * i + 1] = __floats2bfloat162_rn(v.z, v.w);
    } else {
        __shared__ float tile[32][33];
        const int tx = tid & 31, ty = tid >> 5;   // 32 x 8
        if (bx < 128 + 16384 + 1024) {
            int idx = bx - (128 + 16384);
            int n0 = (idx & 31) * 32, k0 = (idx >> 5) * 32;
            #pragma unroll
            for (int j = 0; j < 4; j++)
                tile[ty + 8 * j][tx] = win[(size_t)(k0 + ty + 8 * j) * HD + n0 + tx];
            __syncthreads();
            #pragma unroll
            for (int j = 0; j < 4; j++)
                g_WbTw[(size_t)(n0 + ty + 8 * j) * HD + k0 + tx] =
                    __float2bfloat16(tile[tx][ty + 8 * j]);
        } else {
            int idx = bx - (128 + 16384 + 1024);
            int l = idx / 3072;
            idx -= l * 3072;
            const float* Wg = Wxg + (size_t)l * HD * H2;
            const float* Wc = Wxc + (size_t)l * HD * HD;
            __nv_bfloat16* dst = l ? g_WbT1 : g_WbT0;
            int n0 = (idx % 96) * 32, k0 = (idx / 96) * 32;
            #pragma unroll
            for (int j = 0; j < 4; j++) {
                int k = k0 + ty + 8 * j;
                int n = n0 + tx;
                tile[ty + 8 * j][tx] = (n < 2048) ? Wg[(size_t)k * H2 + n]
                                                  : Wc[(size_t)k * HD + (n - 2048)];
            }
            __syncthreads();
            #pragma unroll
            for (int j = 0; j < 4; j++)
                dst[(size_t)(n0 + ty + 8 * j) * HD + k0 + tx] =
                    __float2bfloat16(tile[tx][ty + 8 * j]);
        }
    }
}

__global__ void k_gather_samp(const int* __restrict__ nce,
                              const float* __restrict__ sw,
                              const float* __restrict__ sb) {
    int s = blockIdx.x;
    int row = nce[s];
    const float* src = sw + (size_t)row * HD;
    for (int k = threadIdx.x; k < HD; k += blockDim.x)
        g_sampWT[k * SD + s] = src[k];
    if (threadIdx.x == 0) g_sampB[s] = sb[row];
}

// ---------------- bf16 mma.sync GEMM, 3-stage cp.async pipeline ----------------
#define LDP 40
#define STG_B 10240u   // bytes per stage per matrix (128 * LDP * 2)

template<bool GATHER, bool BIAS, bool OB16>
__global__ __launch_bounds__(256)
void k_mgemm(const __nv_bfloat16* __restrict__ A, const __nv_bfloat16* __restrict__ BT,
             const float* __restrict__ bias, float* __restrict__ Cf,
             __nv_bfloat16* __restrict__ Cb, int N, const int* __restrict__ gidx)
{
    extern __shared__ __nv_bfloat16 dsm[];
    __nv_bfloat16* sAp = dsm;                   // 3 stages x 128 x LDP
    __nv_bfloat16* sBp = dsm + 3 * 128 * LDP;

    const int tid = threadIdx.x;
    const int rowBase = blockIdx.y * 128;
    const int colBase = blockIdx.x * 128;

    const int lrow = tid & 127;
    const bool isB = tid >= 128;
    const __nv_bfloat16* src;
    if (isB) {
        src = BT + (size_t)(colBase + lrow) * 1024;
    } else {
        size_t ar = GATHER ? (size_t)gidx[rowBase + lrow] : (size_t)(rowBase + lrow);
        src = A + ar * 1024;
    }
    const uint32_t ldBase = s2u(isB ? (const void*)&sBp[lrow * LDP]
                                    : (const void*)&sAp[lrow * LDP]);

    const int wid = tid >> 5, lane = tid & 31;
    const int mb = (wid & 1) * 64;
    const int nb = (wid >> 1) * 32;
    const int arow_l = (lane & 7) + ((lane >> 3) & 1) * 8;
    const int acol_l = (lane >> 4) * 8;
    const int brow_l = (lane & 7) + (lane >> 4) * 8;
    const int bcol_l = ((lane >> 3) & 1) * 8;
    const uint32_t aSB = s2u(sAp);
    const uint32_t bSB = s2u(sBp);

    float acc[4][4][4];
    #pragma unroll
    for (int mt = 0; mt < 4; mt++)
        #pragma unroll
        for (int nt = 0; nt < 4; nt++)
            #pragma unroll
            for (int q = 0; q < 4; q++) acc[mt][nt][q] = 0.f;

    const int S = 32;
    // prologue: stages 0,1
    #pragma unroll
    for (int p = 0; p < 2; p++) {
        uint32_t d = ldBase + (uint32_t)p * STG_B;
        const __nv_bfloat16* q = src + p * 32;
        #pragma unroll
        for (int c = 0; c < 4; c++) cp16(d + c * 16, q + c * 8);
        CP_COMMIT();
    }

    for (int s = 0; s < S; s++) {
        if (s + 2 < S) {
            uint32_t d = ldBase + (uint32_t)((s + 2) % 3) * STG_B;
            const __nv_bfloat16* q = src + (s + 2) * 32;
            #pragma unroll
            for (int c = 0; c < 4; c++) cp16(d + c * 16, q + c * 8);
            CP_COMMIT();
            CP_WAIT(2);
        } else if (s + 1 < S) {
            CP_WAIT(1);
        } else {
            CP_WAIT(0);
        }
        __syncthreads();

        const uint32_t stOff = (uint32_t)(s % 3) * STG_B;
        const uint32_t aS = aSB + stOff;
        const uint32_t bS = bSB + stOff;
        #pragma unroll
        for (int kk = 0; kk < 32; kk += 16) {
            uint32_t af[4][4];
            #pragma unroll
            for (int mt = 0; mt < 4; mt++) {
                uint32_t ad = aS + (uint32_t)(((mb + mt * 16 + arow_l) * LDP) + kk + acol_l) * 2u;
                ldmatrix_x4(af[mt][0], af[mt][1], af[mt][2], af[mt][3], ad);
            }
            uint32_t bf[2][4];
            #pragma unroll
            for (int nt2 = 0; nt2 < 2; nt2++) {
                uint32_t bd = bS + (uint32_t)(((nb + nt2 * 16 + brow_l) * LDP) + kk + bcol_l) * 2u;
                ldmatrix_x4(bf[nt2][0], bf[nt2][1], bf[nt2][2], bf[nt2][3], bd);
            }
            #pragma unroll
            for (int mt = 0; mt < 4; mt++)
                #pragma unroll
                for (int nt = 0; nt < 4; nt++)
                    mma16816(acc[mt][nt], af[mt], &bf[nt >> 1][(nt & 1) * 2]);
        }
        __syncthreads();
    }

    const int erow = lane >> 2;
    const int ecol = (lane & 3) * 2;
    #pragma unroll
    for (int mt = 0; mt < 4; mt++) {
        #pragma unroll
        for (int nt = 0; nt < 4; nt++) {
            int r0 = rowBase + mb + mt * 16 + erow;
            int c0 = colBase + nb + nt * 8 + ecol;
            float b0 = 0.f, b1 = 0.f;
            if (BIAS) { b0 = bias[c0]; b1 = bias[c0 + 1]; }
            float v00 = acc[mt][nt][0] + b0, v01 = acc[mt][nt][1] + b1;
            float v10 = acc[mt][nt][2] + b0, v11 = acc[mt][nt][3] + b1;
            if (OB16) {
                __nv_bfloat162 p0 = __floats2bfloat162_rn(v00, v01);
                __nv_bfloat162 p1 = __floats2bfloat162_rn(v10, v11);
                *(__nv_bfloat162*)&Cb[(size_t)r0 * N + c0] = p0;
                *(__nv_bfloat162*)&Cb[(size_t)(r0 + 8) * N + c0] = p1;
            } else {
                *(float2*)&Cf[(size_t)r0 * N + c0] = make_float2(v00, v01);
                *(float2*)&Cf[(size_t)(r0 + 8) * N + c0] = make_float2(v10, v11);
            }
        }
    }
}

// ---------------- persistent per-layer MI-GRU recurrence (round-12 frozen) ----------
// 128 CTAs x 256 threads. CTA c owns r-gate cols [8c,8c+8), u-gate cols [1024+8c,+8),
// cand cols [8c,+8). u stays in registers across the phase barrier.
// OM==0: write bf16 output only (layer 0). OM==1: write fp32 output only (layer 1).
template<int OM>
__global__ __launch_bounds__(256)
void k_layerX(const float* __restrict__ Whg, const float* __restrict__ Whc,
              const float* __restrict__ XGC,
              const float* __restrict__ ag, const float* __restrict__ b1g,
              const float* __restrict__ b2g, const float* __restrict__ bg,
              const float* __restrict__ ac, const float* __restrict__ b1c,
              const float* __restrict__ b2c, const float* __restrict__ bcv,
              float* __restrict__ outF, __nv_bfloat16* __restrict__ outB,
              unsigned barBase)
{
    extern __shared__ char smRaw[];
    __nv_bfloat16* Wg  = (__nv_bfloat16*)smRaw;       // [16][1032] bf16 = 33024B
    __nv_bfloat16* Wc  = Wg + 16 * 1032;              // [8][1032]  = 16512B
    __nv_bfloat16* stg = Wc + 8 * 1032;               // 4 stages x 128x136 = 139264B

    const int cta = blockIdx.x;
    const int tid = threadIdx.x;
    const int wid = tid >> 5, lane = tid & 31;
    const int col0 = cta * 8;

    for (int i = tid; i < 16 * 1024; i += 256) {
        int n = i & 15, k = i >> 4;
        int col = (n < 8) ? (col0 + n) : (1024 + col0 + (n - 8));
        Wg[n * 1032 + k] = __float2bfloat16(Whg[(size_t)k * H2 + col]);
    }
    for (int i = tid; i < 8 * 1024; i += 256) {
        int n = i & 7, k = i >> 3;
        Wc[n * 1032 + k] = __float2bfloat16(Whc[(size_t)k * HD + col0 + n]);
    }

    const int arow_l = (lane & 7) + ((lane >> 3) & 1) * 8;
    const int acol_l = (lane >> 4) * 8;
    const int brow_l = (lane & 7) + (lane >> 4) * 8;
    const int bcol_l = ((lane >> 3) & 1) * 8;
    const int l16 = lane & 15;

    const uint32_t stB = s2u(stg);
    const uint32_t wgB = s2u(Wg);
    const uint32_t wcB = s2u(Wc);

    const int erow = lane >> 2;
    const int ecol = (lane & 3) * 2;
    const int r0 = wid * 16 + erow;

    float agr[2], b1r[2], b2r[2], bgr[2];
    float agu[2], b1u[2], b2u[2], bgu[2];
    float acv[2], b1cv[2], b2cv[2], bcvv[2];
    #pragma unroll
    for (int j = 0; j < 2; j++) {
        int cr = col0 + ecol + j;
        int cu = 1024 + cr;
        agr[j] = ag[cr]; b1r[j] = b1g[cr]; b2r[j] = b2g[cr]; bgr[j] = bg[cr];
        agu[j] = ag[cu]; b1u[j] = b1g[cu]; b2u[j] = b2g[cu]; bgu[j] = bg[cu];
        acv[j] = ac[cr]; b1cv[j] = b1c[cr]; b2cv[j] = b2c[cr]; bcvv[j] = bcv[cr];
    }

    const int srow = tid & 127;
    const int scb  = (tid >> 7) * 8;
    const uint32_t sdst_off = (uint32_t)(srow * 272 + scb * 16);

    {
        float4 z = make_float4(0.f, 0.f, 0.f, 0.f);
        __stcg((float4*)(g_h + cta * 1024 + tid * 4), z);
        uint2 zb = make_uint2(0u, 0u);
        __stcg((uint2*)(g_hb + cta * 1024 + tid * 4), zb);
    }
    unsigned bar = barBase + 1;
    gsync(bar);

    for (int t = 0; t < TD; t++) {
        const float* Xt = XGC + (size_t)t * BD * NG;
        float ur[2][2];
        float2 hvp[2];

        // ================= gate phase =================
        {
            float2 gxr[2], gxu[2];
            #pragma unroll
            for (int half = 0; half < 2; half++) {
                int row = r0 + half * 8;
                gxr[half] = __ldcg((const float2*)(Xt + (size_t)row * NG + col0 + ecol));
                gxu[half] = __ldcg((const float2*)(Xt + (size_t)row * NG + 1024 + col0 + ecol));
                hvp[half] = __ldcg((const float2*)(g_h + (size_t)row * 1024 + col0 + ecol));
            }

            float acc[2][4];
            #pragma unroll
            for (int nt = 0; nt < 2; nt++)
                #pragma unroll
                for (int q = 0; q < 4; q++) acc[nt][q] = 0.f;

            #pragma unroll
            for (int p = 0; p < 3; p++) {
                const __nv_bfloat16* src = g_hb + (size_t)srow * 1024 + p * 128 + scb * 8;
                uint32_t dst = stB + (uint32_t)p * 34816u + sdst_off;
                #pragma unroll
                for (int c = 0; c < 8; c++) cp16(dst + c * 16, src + c * 8);
                CP_COMMIT();
            }
            for (int chunk = 0; chunk < 8; chunk++) {
                if (chunk < 5) {
                    const __nv_bfloat16* src = g_hb + (size_t)srow * 1024 + (chunk + 3) * 128 + scb * 8;
                    uint32_t dst = stB + (uint32_t)((chunk + 3) & 3) * 34816u + sdst_off;
                    #pragma unroll
                    for (int c = 0; c < 8; c++) cp16(dst + c * 16, src + c * 8);
                    CP_COMMIT();
                    CP_WAIT(3);
                } else {
                    CP_WAIT(0);
                }
                __syncthreads();
                uint32_t aB = stB + (uint32_t)(chunk & 3) * 34816u;
                #pragma unroll
                for (int ks = 0; ks < 8; ks++) {
                    int kloc = ks * 16;
                    int kg = chunk * 128 + kloc;
                    uint32_t af[4];
                    ldmatrix_x4(af[0], af[1], af[2], af[3],
                        aB + (uint32_t)((wid * 16 + arow_l) * 272 + (kloc + acol_l) * 2));
                    uint32_t bf[4];
                    ldmatrix_x4(bf[0], bf[1], bf[2], bf[3],
                        wgB + (uint32_t)(brow_l * 2064 + (kg + bcol_l) * 2));
                    mma16816(acc[0], af, &bf[0]);
                    mma16816(acc[1], af, &bf[2]);
                }
                __syncthreads();
            }

            #pragma unroll
            for (int half = 0; half < 2; half++) {
                int row = r0 + half * 8;
                float gh0 = acc[0][half * 2 + 0], gh1 = acc[0][half * 2 + 1];
                float z0 = agr[0] * gxr[half].x * gh0 + b1r[0] * gxr[half].x + b2r[0] * gh0 + bgr[0];
                float z1 = agr[1] * gxr[half].y * gh1 + b1r[1] * gxr[half].y + b2r[1] * gh1 + bgr[1];
                float s0 = 1.f / (1.f + expf(-z0));
                float s1 = 1.f / (1.f + expf(-z1));
                __nv_bfloat162 p = __floats2bfloat162_rn(s0 * hvp[half].x, s1 * hvp[half].y);
                __stcg((uint32_t*)(g_RHb + (size_t)row * 1024 + col0 + ecol), *(uint32_t*)&p);

                float uh0 = acc[1][half * 2 + 0], uh1 = acc[1][half * 2 + 1];
                float y0 = agu[0] * gxu[half].x * uh0 + b1u[0] * gxu[half].x + b2u[0] * uh0 + bgu[0];
                float y1 = agu[1] * gxu[half].y * uh1 + b1u[1] * gxu[half].y + b2u[1] * uh1 + bgu[1];
                ur[half][0] = 1.f / (1.f + expf(-y0));
                ur[half][1] = 1.f / (1.f + expf(-y1));
            }
        }
        bar++; gsync(bar);

        // ================= cand phase =================
        {
            float2 cxv[2];
            #pragma unroll
            for (int half = 0; half < 2; half++) {
                int row = r0 + half * 8;
                cxv[half] = __ldcg((const float2*)(Xt + (size_t)row * NG + 2048 + col0 + ecol));
            }

            float acc[4] = {0.f, 0.f, 0.f, 0.f};
            #pragma unroll
            for (int p = 0; p < 3; p++) {
                const __nv_bfloat16* src = g_RHb + (size_t)srow * 1024 + p * 128 + scb * 8;
                uint32_t dst = stB + (uint32_t)p * 34816u + sdst_off;
                #pragma unroll
                for (int c = 0; c < 8; c++) cp16(dst + c * 16, src + c * 8);
                CP_COMMIT();
            }
            for (int chunk = 0; chunk < 8; chunk++) {
                if (chunk < 5) {
                    const __nv_bfloat16* src = g_RHb + (size_t)srow * 1024 + (chunk + 3) * 128 + scb * 8;
                    uint32_t dst = stB + (uint32_t)((chunk + 3) & 3) * 34816u + sdst_off;
                    #pragma unroll
                    for (int c = 0; c < 8; c++) cp16(dst + c * 16, src + c * 8);
                    CP_COMMIT();
                    CP_WAIT(3);
                } else {
                    CP_WAIT(0);
                }
                __syncthreads();
                uint32_t aB = stB + (uint32_t)(chunk & 3) * 34816u;
                #pragma unroll
                for (int ks = 0; ks < 8; ks++) {
                    int kloc = ks * 16;
                    int kg = chunk * 128 + kloc;
                    uint32_t af[4];
                    ldmatrix_x4(af[0], af[1], af[2], af[3],
                        aB + (uint32_t)((wid * 16 + arow_l) * 272 + (kloc + acol_l) * 2));
                    uint32_t bf2[2];
                    ldmatrix_x2(bf2[0], bf2[1],
                        wcB + (uint32_t)((l16 & 7) * 2064 + (kg + (l16 >> 3) * 8) * 2));
                    mma16816(acc, af, bf2);
                }
                __syncthreads();
            }

            #pragma unroll
            for (int half = 0; half < 2; half++) {
                int row = r0 + half * 8;
                float ch0 = acc[half * 2 + 0], ch1 = acc[half * 2 + 1];
                float z0 = acv[0] * cxv[half].x * ch0 + b1cv[0] * cxv[half].x + b2cv[0] * ch0 + bcvv[0];
                float z1 = acv[1] * cxv[half].y * ch1 + b1cv[1] * cxv[half].y + b2cv[1] * ch1 + bcvv[1];
                float c0 = tanhf(z0), c1 = tanhf(z1);
                float hn0 = ur[half][0] * hvp[half].x + (1.f - ur[half][0]) * c0;
                float hn1 = ur[half][1] * hvp[half].y + (1.f - ur[half][1]) * c1;
                __stcg((float2*)(g_h + (size_t)row * 1024 + col0 + ecol), make_float2(hn0, hn1));
                __nv_bfloat162 p = __floats2bfloat162_rn(hn0, hn1);
                __stcg((uint32_t*)(g_hb + (size_t)row * 1024 + col0 + ecol), *(uint32_t*)&p);
                size_t off = (size_t)t * BD * HD + (size_t)row * HD + col0 + ecol;
                if (OM == 0)
                    *(__nv_bfloat162*)(outB + off) = p;
                else
                    *(float2*)(outF + off) = make_float2(hn0, hn1);
            }
        }
        bar++; gsync(bar);
    }
}

// ---------------- NCE ----------------
__global__ __launch_bounds__(256)
void k_nce_samp(float* __restrict__ outsum)
{
    __shared__ float As[8][132];
    __shared__ float Bs[8][64];
    __shared__ float red[256];
    const int tid = threadIdx.x;
    const int rowBase = blockIdx.x * 128;

    const int arow = tid >> 1;
    const int acol = (tid & 1) << 2;
    int gi = rowBase + arow;
    size_t aoff = (size_t)((gi & 255) * BD + (gi >> 8)) * HD;

    const int brow = tid >> 5;
    const int bcl  = (tid & 31) << 1;
    const int ty = tid >> 4;
    const int tx = tid & 15;

    float acc[8][4];
    #pragma unroll
    for (int i = 0; i < 8; i++)
        #pragma unroll
        for (int j = 0; j < 4; j++) acc[i][j] = 0.f;

    for (int k0 = 0; k0 < HD; k0 += 8) {
        float4 av = *(const float4*)(g_O1 + aoff + k0 + acol);
        As[acol + 0][arow] = av.x;
        As[acol + 1][arow] = av.y;
        As[acol + 2][arow] = av.z;
        As[acol + 3][arow] = av.w;
        float2 bw = *(const float2*)(g_sampWT + (size_t)(k0 + brow) * SD + bcl);
        Bs[brow][bcl]     = bw.x;
        Bs[brow][bcl + 1] = bw.y;
        __syncthreads();
        #pragma unroll
        for (int k = 0; k < 8; k++) {
            float ar[8], br[4];
            *(float4*)&ar[0] = *(const float4*)&As[k][ty * 8];
            *(float4*)&ar[4] = *(const float4*)&As[k][ty * 8 + 4];
            *(float4*)&br[0] = *(const float4*)&Bs[k][tx * 4];
            #pragma unroll
            for (int i = 0; i < 8; i++)
                #pragma unroll
                for (int j = 0; j < 4; j++)
                    acc[i][j] += ar[i] * br[j];
        }
        __syncthreads();
    }

    float s = 0.f;
    #pragma unroll
    for (int j = 0; j < 4; j++) {
        float sbv = g_sampB[tx * 4 + j];
        #pragma unroll
        for (int i = 0; i < 8; i++)
            s += softplusf(acc[i][j] + sbv);
    }
    red[tid] = s;
    __syncthreads();
    for (int o = 128; o > 0; o >>= 1) {
        if (tid < o) red[tid] += red[tid + o];
        __syncthreads();
    }
    if (tid == 0) atomicAdd(outsum, red[0] * (1.f / 32768.f));
}

__global__ __launch_bounds__(256)
void k_nce_true(const int* __restrict__ targets, const float* __restrict__ sw,
                const float* __restrict__ sb, float* __restrict__ outsum)
{
    __shared__ float red[8];
    const int warp = threadIdx.x >> 5;
    const int lane = threadIdx.x & 31;
    const int i = blockIdx.x * 8 + warp;
    const int label = targets[i];
    const float* orow = g_O1 + (size_t)((i & 255) * BD + (i >> 8)) * HD;
    const float* wrow = sw + (size_t)label * HD;

    float s = 0.f;
    #pragma unroll
    for (int k0 = 0; k0 < HD; k0 += 128) {
        float4 a = *(const float4*)(orow + k0 + lane * 4);
        float4 w = *(const float4*)(wrow + k0 + lane * 4);
        s += a.x * w.x + a.y * w.y + a.z * w.z + a.w * w.w;
    }
    #pragma unroll
    for (int o = 16; o > 0; o >>= 1) s += __shfl_xor_sync(0xffffffffu, s, o);
    if (lane == 0) {
        float logit = s + sb[label];
        red[warp] = softplusf(-logit);
    }
    __syncthreads();
    if (threadIdx.x == 0) {
        float t = 0.f;
        #pragma unroll
        for (int w = 0; w < 8; w++) t += red[w];
        atomicAdd(outsum, t * (1.f / 32768.f));
    }
}

// ---------------- launch ----------------
extern "C" void kernel_launch(void* const* d_in, const int* in_sizes, int n_in,
                              void* d_out, int out_size)
{
    const int*   input_data = (const int*)  d_in[0];
    const int*   targets    = (const int*)  d_in[1];
    const int*   nce        = (const int*)  d_in[2];
    const float* embedding  = (const float*)d_in[3];
    const float* win        = (const float*)d_in[4];
    const float* bin_       = (const float*)d_in[5];
    const float* Wxg        = (const float*)d_in[6];
    const float* Whg        = (const float*)d_in[7];
    const float* ag         = (const float*)d_in[8];
    const float* b1g        = (const float*)d_in[9];
    const float* b2g        = (const float*)d_in[10];
    const float* bg         = (const float*)d_in[11];
    const float* Wxc        = (const float*)d_in[12];
    const float* Whc        = (const float*)d_in[13];
    const float* ac         = (const float*)d_in[14];
    const float* b1c        = (const float*)d_in[15];
    const float* b2c        = (const float*)d_in[16];
    const float* bc         = (const float*)d_in[17];
    const float* softmax_w  = (const float*)d_in[18];
    const float* softmax_b  = (const float*)d_in[19];
    float* out = (float*)d_out;

    float *pXGC, *pO1;
    int* pidx;
    __nv_bfloat16 *pAb, *pEb, *pWbTw, *pWbT0, *pWbT1, *pO0b;
    cudaGetSymbolAddress((void**)&pXGC, g_XGC);
    cudaGetSymbolAddress((void**)&pO1,  g_O1);
    cudaGetSymbolAddress((void**)&pO0b, g_O0b);
    cudaGetSymbolAddress((void**)&pidx, g_rowidx);
    cudaGetSymbolAddress((void**)&pAb,  g_Ab);
    cudaGetSymbolAddress((void**)&pEb,  g_Eb);
    cudaGetSymbolAddress((void**)&pWbTw, g_WbTw);
    cudaGetSymbolAddress((void**)&pWbT0, g_WbT0);
    cudaGetSymbolAddress((void**)&pWbT1, g_WbT1);

    cudaFuncSetAttribute(k_layerX<0>,
                         cudaFuncAttributeMaxDynamicSharedMemorySize, 188800);
    cudaFuncSetAttribute(k_layerX<1>,
                         cudaFuncAttributeMaxDynamicSharedMemorySize, 188800);
    cudaFuncSetAttribute(k_mgemm<true, true, true>,
                         cudaFuncAttributeMaxDynamicSharedMemorySize, 61440);
    cudaFuncSetAttribute(k_mgemm<false, false, false>,
                         cudaFuncAttributeMaxDynamicSharedMemorySize, 61440);

    // launch 0: setup + embedding->bf16 + all weight transposes
    k_convW<<<128 + 16384 + 1024 + 3072 + 3072, 256>>>(
        input_data, out, out_size, embedding, win, Wxg, Wxc);

    // launch 1: X(bf16) = gather(Eb) @ win + bin_   -> g_Ab directly
    k_mgemm<true, true, true><<<dim3(HD / 128, TB / 128), 256, 61440>>>(
        pEb, pWbTw, bin_, nullptr, pAb, HD, pidx);

    // launch 2: XGC = Ab @ [Wxg0|Wxc0]
    k_mgemm<false, false, false><<<dim3(NG / 128, TB / 128), 256, 61440>>>(
        pAb, pWbT0, nullptr, pXGC, nullptr, NG, nullptr);

    // launch 3: layer-0 recurrence (bf16 output only)
    k_layerX<0><<<128, 256, 188800>>>(
        Whg, Whc, pXGC,
        ag, b1g, b2g, bg, ac, b1c, b2c, bc,
        nullptr, pO0b, 0u);

    // launch 4: XGC = O0b @ [Wxg1|Wxc1]
    k_mgemm<false, false, false><<<dim3(NG / 128, TB / 128), 256, 61440>>>(
        pO0b, pWbT1, nullptr, pXGC, nullptr, NG, nullptr);

    // launch 5: layer-1 recurrence (fp32 output only)
    k_layerX<1><<<128, 256, 188800>>>(
        Whg + (size_t)HD * H2, Whc + (size_t)HD * HD, pXGC,
        ag + H2, b1g + H2, b2g + H2, bg + H2,
        ac + HD, b1c + HD, b2c + HD, bc + HD,
        pO1, nullptr, 1u + 2u * TD);

    // NCE
    k_gather_samp<<<SD, 256>>>(nce, softmax_w, softmax_b);
    k_nce_true<<<TB / 8, 256>>>(targets, softmax_w, softmax_b, out);
    k_nce_samp<<<TB / 128, 256>>>(out);
}

// round 17
// speedup vs baseline: 1.0768x; 1.0037x over previous
#include <cuda_runtime.h>
#include <cuda_bf16.h>
#include <stdint.h>
#include <math.h>

// Problem constants
#define VD 16384
#define ED 1024
#define HD 1024
#define H2 2048
#define LD 2
#define BD 128
#define TD 256
#define SD 64
#define TB 32768   // B*T
#define NG 3072    // fused gate+cand projection width

// ---------------- scratch (__device__ globals; no allocations allowed) -------------
__device__ float g_XGC0[(size_t)TB * NG];  // layer-0 x-projections
__device__ float g_XGC1[(size_t)TB * NG];  // layer-1 x-projections (worker-produced)
__device__ float g_O1 [(size_t)TB * HD];   // layer-1 fp32 outputs (NCE input)
__device__ __nv_bfloat16 g_O0b[(size_t)TB * HD];  // layer-0 bf16 outputs
__device__ float g_h [BD * HD];
__device__ __nv_bfloat16 g_hb [BD * HD];
__device__ __nv_bfloat16 g_RHb[BD * HD];
__device__ float g_sampWT[HD * SD];
__device__ float g_sampB [SD];
__device__ int   g_rowidx[TB];
__device__ unsigned g_barcnt;

__device__ __nv_bfloat16 g_Ab  [(size_t)TB * HD];  // X in bf16 (layer-0 A operand)
__device__ __nv_bfloat16 g_Eb  [(size_t)VD * ED];
__device__ __nv_bfloat16 g_WbTw[(size_t)HD * HD];  // win^T bf16
__device__ __nv_bfloat16 g_WbT0[(size_t)NG * HD];  // [Wxg0|Wxc0]^T bf16
__device__ __nv_bfloat16 g_WbT1[(size_t)NG * HD];  // [Wxg1|Wxc1]^T bf16

__device__ __forceinline__ float softplusf(float x) {
    return fmaxf(x, 0.f) + log1pf(expf(-fabsf(x)));
}

// ---------------- PTX helpers ----------------
__device__ __forceinline__ uint32_t s2u(const void* p) {
    uint32_t a;
    asm("{ .reg .u64 t; cvta.to.shared.u64 t, %1; cvt.u32.u64 %0, t; }" : "=r"(a) : "l"(p));
    return a;
}
__device__ __forceinline__ void cp16(uint32_t dst, const void* src) {
    asm volatile("cp.async.cg.shared.global [%0], [%1], 16;" :: "r"(dst), "l"(src));
}
#define CP_COMMIT() asm volatile("cp.async.commit_group;" ::: "memory")
#define CP_WAIT(n)  asm volatile("cp.async.wait_group %0;" :: "n"(n) : "memory")

__device__ __forceinline__ void ldmatrix_x4(uint32_t& r0, uint32_t& r1,
                                            uint32_t& r2, uint32_t& r3, uint32_t addr) {
    asm volatile("ldmatrix.sync.aligned.m8n8.x4.shared.b16 {%0,%1,%2,%3}, [%4];"
                 : "=r"(r0), "=r"(r1), "=r"(r2), "=r"(r3) : "r"(addr));
}
__device__ __forceinline__ void ldmatrix_x2(uint32_t& r0, uint32_t& r1, uint32_t addr) {
    asm volatile("ldmatrix.sync.aligned.m8n8.x2.shared.b16 {%0,%1}, [%2];"
                 : "=r"(r0), "=r"(r1) : "r"(addr));
}
__device__ __forceinline__ void mma16816(float* d, const uint32_t* a, const uint32_t* b) {
    asm volatile("mma.sync.aligned.m16n8k16.row.col.f32.bf16.bf16.f32 "
                 "{%0,%1,%2,%3},{%4,%5,%6,%7},{%8,%9},{%0,%1,%2,%3};"
                 : "+f"(d[0]), "+f"(d[1]), "+f"(d[2]), "+f"(d[3])
                 : "r"(a[0]), "r"(a[1]), "r"(a[2]), "r"(a[3]), "r"(b[0]), "r"(b[1]));
}

// single-counter software grid barrier — FIXED: target = index * 128 arrivals.
// idx is globally monotonic across both layer launches. 128 recurrence CTAs arrive.
__device__ __forceinline__ void gsync(unsigned idx) {
    __syncthreads();
    if (threadIdx.x == 0) {
        __threadfence();
        atomicAdd(&g_barcnt, 1u);
        const unsigned target = idx * 128u;
        while (*(volatile unsigned*)&g_barcnt < target) __nanosleep(16);
        __threadfence();
    }
    __syncthreads();
}

// acquire-poll for worker CTAs pacing on the barrier counter
__device__ __forceinline__ void wait_barcnt(unsigned target) {
    unsigned v;
    asm volatile("ld.acquire.gpu.global.u32 %0, [%1];" : "=r"(v) : "l"(&g_barcnt) : "memory");
    while (v < target) {
        __nanosleep(64);
        asm volatile("ld.acquire.gpu.global.u32 %0, [%1];" : "=r"(v) : "l"(&g_barcnt) : "memory");
    }
}

// ---------------- upfront fused kernel: setup + emb->bf16 + ALL weight transposes ---
__global__ void k_convW(const int* __restrict__ input_data, float* out, int out_size,
                        const float* __restrict__ emb, const float* __restrict__ win,
                        const float* __restrict__ Wxg, const float* __restrict__ Wxc)
{
    const int bx = blockIdx.x;
    const int tid = threadIdx.x;
    if (bx < 128) {
        if (bx == 0 && tid == 0) {
            g_barcnt = 0u;
            for (int i = 0; i < out_size; i++) out[i] = 0.f;
        }
        int r = bx * 256 + tid;
        int t = r >> 7, b = r & 127;
        g_rowidx[r] = input_data[b * TD + t];
    } else if (bx < 128 + 16384) {
        int i = (bx - 128) * 256 + tid;
        float4 v = ((const float4*)emb)[i];
        __nv_bfloat162* o = (__nv_bfloat162*)g_Eb;
        o[2 * i + 0] = __floats2bfloat162_rn(v.x, v.y);
        o[2 * i + 1] = __floats2bfloat162_rn(v.z, v.w);
    } else {
        __shared__ float tile[32][33];
        const int tx = tid & 31, ty = tid >> 5;   // 32 x 8
        if (bx < 128 + 16384 + 1024) {
            int idx = bx - (128 + 16384);
            int n0 = (idx & 31) * 32, k0 = (idx >> 5) * 32;
            #pragma unroll
            for (int j = 0; j < 4; j++)
                tile[ty + 8 * j][tx] = win[(size_t)(k0 + ty + 8 * j) * HD + n0 + tx];
            __syncthreads();
            #pragma unroll
            for (int j = 0; j < 4; j++)
                g_WbTw[(size_t)(n0 + ty + 8 * j) * HD + k0 + tx] =
                    __float2bfloat16(tile[tx][ty + 8 * j]);
        } else {
            int idx = bx - (128 + 16384 + 1024);
            int l = idx / 3072;
            idx -= l * 3072;
            const float* Wg = Wxg + (size_t)l * HD * H2;
            const float* Wc = Wxc + (size_t)l * HD * HD;
            __nv_bfloat16* dst = l ? g_WbT1 : g_WbT0;
            int n0 = (idx % 96) * 32, k0 = (idx / 96) * 32;
            #pragma unroll
            for (int j = 0; j < 4; j++) {
                int k = k0 + ty + 8 * j;
                int n = n0 + tx;
                tile[ty + 8 * j][tx] = (n < 2048) ? Wg[(size_t)k * H2 + n]
                                                  : Wc[(size_t)k * HD + (n - 2048)];
            }
            __syncthreads();
            #pragma unroll
            for (int j = 0; j < 4; j++)
                dst[(size_t)(n0 + ty + 8 * j) * HD + k0 + tx] =
                    __float2bfloat16(tile[tx][ty + 8 * j]);
        }
    }
}

__global__ void k_gather_samp(const int* __restrict__ nce,
                              const float* __restrict__ sw,
                              const float* __restrict__ sb) {
    int s = blockIdx.x;
    int row = nce[s];
    const float* src = sw + (size_t)row * HD;
    for (int k = threadIdx.x; k < HD; k += blockDim.x)
        g_sampWT[k * SD + s] = src[k];
    if (threadIdx.x == 0) g_sampB[s] = sb[row];
}

// ---------------- bf16 mma.sync GEMM (2-stage; round-12 proven) ----------------
#define LDP 40

template<bool GATHER, bool BIAS, bool OB16>
__global__ __launch_bounds__(256)
void k_mgemm(const __nv_bfloat16* __restrict__ A, const __nv_bfloat16* __restrict__ BT,
             const float* __restrict__ bias, float* __restrict__ Cf,
             __nv_bfloat16* __restrict__ Cb, int N, const int* __restrict__ gidx)
{
    __shared__ __align__(16) __nv_bfloat16 sA[2][128 * LDP];
    __shared__ __align__(16) __nv_bfloat16 sB[2][128 * LDP];

    const int tid = threadIdx.x;
    const int rowBase = blockIdx.y * 128;
    const int colBase = blockIdx.x * 128;

    const int lrow = tid & 127;
    const bool isB = tid >= 128;
    const __nv_bfloat16* src;
    if (isB) {
        src = BT + (size_t)(colBase + lrow) * 1024;
    } else {
        size_t ar = GATHER ? (size_t)gidx[rowBase + lrow] : (size_t)(rowBase + lrow);
        src = A + ar * 1024;
    }
    uint32_t dst0 = s2u(isB ? (const void*)&sB[0][lrow * LDP] : (const void*)&sA[0][lrow * LDP]);
    uint32_t dst1 = s2u(isB ? (const void*)&sB[1][lrow * LDP] : (const void*)&sA[1][lrow * LDP]);

    const int wid = tid >> 5, lane = tid & 31;
    const int mb = (wid & 1) * 64;
    const int nb = (wid >> 1) * 32;
    const int arow_l = (lane & 7) + ((lane >> 3) & 1) * 8;
    const int acol_l = (lane >> 4) * 8;
    const int brow_l = (lane & 7) + (lane >> 4) * 8;
    const int bcol_l = ((lane >> 3) & 1) * 8;
    const uint32_t aS0 = s2u(sA[0]), aS1 = s2u(sA[1]);
    const uint32_t bS0 = s2u(sB[0]), bS1 = s2u(sB[1]);

    float acc[4][4][4];
    #pragma unroll
    for (int mt = 0; mt < 4; mt++)
        #pragma unroll
        for (int nt = 0; nt < 4; nt++)
            #pragma unroll
            for (int q = 0; q < 4; q++) acc[mt][nt][q] = 0.f;

    const int S = 32;
    {
        const __nv_bfloat16* p = src;
        #pragma unroll
        for (int c = 0; c < 4; c++) cp16(dst0 + c * 16, p + c * 8);
        CP_COMMIT();
    }

    for (int s = 0; s < S; s++) {
        if (s + 1 < S) {
            uint32_t d = ((s + 1) & 1) ? dst1 : dst0;
            const __nv_bfloat16* p = src + (s + 1) * 32;
            #pragma unroll
            for (int c = 0; c < 4; c++) cp16(d + c * 16, p + c * 8);
            CP_COMMIT();
            CP_WAIT(1);
        } else {
            CP_WAIT(0);
        }
        __syncthreads();

        const uint32_t aS = (s & 1) ? aS1 : aS0;
        const uint32_t bS = (s & 1) ? bS1 : bS0;
        #pragma unroll
        for (int kk = 0; kk < 32; kk += 16) {
            uint32_t af[4][4];
            #pragma unroll
            for (int mt = 0; mt < 4; mt++) {
                uint32_t ad = aS + (uint32_t)(((mb + mt * 16 + arow_l) * LDP) + kk + acol_l) * 2u;
                ldmatrix_x4(af[mt][0], af[mt][1], af[mt][2], af[mt][3], ad);
            }
            uint32_t bf[2][4];
            #pragma unroll
            for (int nt2 = 0; nt2 < 2; nt2++) {
                uint32_t bd = bS + (uint32_t)(((nb + nt2 * 16 + brow_l) * LDP) + kk + bcol_l) * 2u;
                ldmatrix_x4(bf[nt2][0], bf[nt2][1], bf[nt2][2], bf[nt2][3], bd);
            }
            #pragma unroll
            for (int mt = 0; mt < 4; mt++)
                #pragma unroll
                for (int nt = 0; nt < 4; nt++)
                    mma16816(acc[mt][nt], af[mt], &bf[nt >> 1][(nt & 1) * 2]);
        }
        __syncthreads();
    }

    const int erow = lane >> 2;
    const int ecol = (lane & 3) * 2;
    #pragma unroll
    for (int mt = 0; mt < 4; mt++) {
        #pragma unroll
        for (int nt = 0; nt < 4; nt++) {
            int r0 = rowBase + mb + mt * 16 + erow;
            int c0 = colBase + nb + nt * 8 + ecol;
            float b0 = 0.f, b1 = 0.f;
            if (BIAS) { b0 = bias[c0]; b1 = bias[c0 + 1]; }
            float v00 = acc[mt][nt][0] + b0, v01 = acc[mt][nt][1] + b1;
            float v10 = acc[mt][nt][2] + b0, v11 = acc[mt][nt][3] + b1;
            if (OB16) {
                __nv_bfloat162 p0 = __floats2bfloat162_rn(v00, v01);
                __nv_bfloat162 p1 = __floats2bfloat162_rn(v10, v11);
                *(__nv_bfloat162*)&Cb[(size_t)r0 * N + c0] = p0;
                *(__nv_bfloat162*)&Cb[(size_t)(r0 + 8) * N + c0] = p1;
            } else {
                *(float2*)&Cf[(size_t)r0 * N + c0] = make_float2(v00, v01);
                *(float2*)&Cf[(size_t)(r0 + 8) * N + c0] = make_float2(v10, v11);
            }
        }
    }
}

// ---------------- persistent per-layer MI-GRU recurrence ----------------------------
// CTAs [0,128): recurrence (round-12 structure, CORRECT barrier). CTA c owns r-gate
// cols [8c,+8), u-gate cols [1024+8c,+8), cand cols [8c,+8); u carried in registers.
// NW>0 (layer 0 only): CTAs [128,128+NW) are GEMM workers computing
// g_XGC1 = O0b @ WbT1, tile (t, ncol); tile row t legal once barrier 3+2t done.
template<int OM, int NW>
__global__ __launch_bounds__(256)
void k_layerX(const float* __restrict__ Whg, const float* __restrict__ Whc,
              const float* __restrict__ XGC,
              const float* __restrict__ ag, const float* __restrict__ b1g,
              const float* __restrict__ b2g, const float* __restrict__ bg,
              const float* __restrict__ ac, const float* __restrict__ b1c,
              const float* __restrict__ b2c, const float* __restrict__ bcv,
              float* __restrict__ outF, __nv_bfloat16* __restrict__ outB,
              unsigned barBase)
{
    extern __shared__ char smRaw[];
    __nv_bfloat16* Wg  = (__nv_bfloat16*)smRaw;       // [16][1032] bf16 = 33024B
    __nv_bfloat16* Wc  = Wg + 16 * 1032;              // [8][1032]  = 16512B
    __nv_bfloat16* stg = Wc + 8 * 1032;               // 4 stages x 128x136 = 139264B

    const int cta = blockIdx.x;
    const int tid = threadIdx.x;
    const int wid = tid >> 5, lane = tid & 31;

    // =================== GEMM worker path (layer-0 launch only) ===================
    if (NW > 0 && cta >= 128) {
        const int wrk = cta - 128;
        __nv_bfloat16* sA = stg;                       // 2 stages x 128 x LDP
        __nv_bfloat16* sB = stg + 2 * 128 * LDP;

        const int lrow = tid & 127;
        const bool isB = tid >= 128;
        uint32_t dst0 = s2u(isB ? (const void*)&sB[0 * 128 * LDP + lrow * LDP]
                                : (const void*)&sA[0 * 128 * LDP + lrow * LDP]);
        uint32_t dst1 = s2u(isB ? (const void*)&sB[1 * 128 * LDP + lrow * LDP]
                                : (const void*)&sA[1 * 128 * LDP + lrow * LDP]);
        const int mb = (wid & 1) * 64;
        const int nb = (wid >> 1) * 32;
        const int arow_l = (lane & 7) + ((lane >> 3) & 1) * 8;
        const int acol_l = (lane >> 4) * 8;
        const int brow_l = (lane & 7) + (lane >> 4) * 8;
        const int bcol_l = ((lane >> 3) & 1) * 8;
        const uint32_t aS0 = s2u(sA), aS1 = s2u(sA + 128 * LDP);
        const uint32_t bS0 = s2u(sB), bS1 = s2u(sB + 128 * LDP);
        const int erow = lane >> 2;
        const int ecol = (lane & 3) * 2;

        for (int tile = wrk; tile < 256 * 24; tile += NW) {
            const int r  = tile / 24;          // timestep / block-row
            const int nc = tile - r * 24;      // block-col
            // wait until layer-0 step r's cand barrier (index 3+2r) completed
            if (tid == 0) wait_barcnt((unsigned)(3 + 2 * r) * 128u);
            __syncthreads();

            const __nv_bfloat16* src = isB
                ? (g_WbT1 + (size_t)(nc * 128 + lrow) * 1024)
                : (g_O0b  + (size_t)(r * 128 + lrow) * 1024);

            float acc[4][4][4];
            #pragma unroll
            for (int mt = 0; mt < 4; mt++)
                #pragma unroll
                for (int nt = 0; nt < 4; nt++)
                    #pragma unroll
                    for (int q = 0; q < 4; q++) acc[mt][nt][q] = 0.f;

            {
                #pragma unroll
                for (int c = 0; c < 4; c++) cp16(dst0 + c * 16, src + c * 8);
                CP_COMMIT();
            }
            for (int s = 0; s < 32; s++) {
                if (s + 1 < 32) {
                    uint32_t d = ((s + 1) & 1) ? dst1 : dst0;
                    const __nv_bfloat16* p = src + (s + 1) * 32;
                    #pragma unroll
                    for (int c = 0; c < 4; c++) cp16(d + c * 16, p + c * 8);
                    CP_COMMIT();
                    CP_WAIT(1);
                } else {
                    CP_WAIT(0);
                }
                __syncthreads();
                const uint32_t aS = (s & 1) ? aS1 : aS0;
                const uint32_t bS = (s & 1) ? bS1 : bS0;
                #pragma unroll
                for (int kk = 0; kk < 32; kk += 16) {
                    uint32_t af[4][4];
                    #pragma unroll
                    for (int mt = 0; mt < 4; mt++) {
                        uint32_t ad = aS + (uint32_t)(((mb + mt * 16 + arow_l) * LDP) + kk + acol_l) * 2u;
                        ldmatrix_x4(af[mt][0], af[mt][1], af[mt][2], af[mt][3], ad);
                    }
                    uint32_t bf[2][4];
                    #pragma unroll
                    for (int nt2 = 0; nt2 < 2; nt2++) {
                        uint32_t bd = bS + (uint32_t)(((nb + nt2 * 16 + brow_l) * LDP) + kk + bcol_l) * 2u;
                        ldmatrix_x4(bf[nt2][0], bf[nt2][1], bf[nt2][2], bf[nt2][3], bd);
                    }
                    #pragma unroll
                    for (int mt = 0; mt < 4; mt++)
                        #pragma unroll
                        for (int nt = 0; nt < 4; nt++)
                            mma16816(acc[mt][nt], af[mt], &bf[nt >> 1][(nt & 1) * 2]);
                }
                __syncthreads();
            }

            #pragma unroll
            for (int mt = 0; mt < 4; mt++) {
                #pragma unroll
                for (int nt = 0; nt < 4; nt++) {
                    int r0 = r * 128 + mb + mt * 16 + erow;
                    int c0 = nc * 128 + nb + nt * 8 + ecol;
                    *(float2*)&g_XGC1[(size_t)r0 * NG + c0] =
                        make_float2(acc[mt][nt][0], acc[mt][nt][1]);
                    *(float2*)&g_XGC1[(size_t)(r0 + 8) * NG + c0] =
                        make_float2(acc[mt][nt][2], acc[mt][nt][3]);
                }
            }
            __syncthreads();
        }
        return;
    }

    // =================== recurrence path ===================
    const int col0 = cta * 8;

    for (int i = tid; i < 16 * 1024; i += 256) {
        int n = i & 15, k = i >> 4;
        int col = (n < 8) ? (col0 + n) : (1024 + col0 + (n - 8));
        Wg[n * 1032 + k] = __float2bfloat16(Whg[(size_t)k * H2 + col]);
    }
    for (int i = tid; i < 8 * 1024; i += 256) {
        int n = i & 7, k = i >> 3;
        Wc[n * 1032 + k] = __float2bfloat16(Whc[(size_t)k * HD + col0 + n]);
    }

    const int arow_l = (lane & 7) + ((lane >> 3) & 1) * 8;
    const int acol_l = (lane >> 4) * 8;
    const int brow_l = (lane & 7) + (lane >> 4) * 8;
    const int bcol_l = ((lane >> 3) & 1) * 8;
    const int l16 = lane & 15;

    const uint32_t stB = s2u(stg);
    const uint32_t wgB = s2u(Wg);
    const uint32_t wcB = s2u(Wc);

    const int erow = lane >> 2;
    const int ecol = (lane & 3) * 2;
    const int r0 = wid * 16 + erow;

    float agr[2], b1r[2], b2r[2], bgr[2];
    float agu[2], b1u[2], b2u[2], bgu[2];
    float acv[2], b1cv[2], b2cv[2], bcvv[2];
    #pragma unroll
    for (int j = 0; j < 2; j++) {
        int cr = col0 + ecol + j;
        int cu = 1024 + cr;
        agr[j] = ag[cr]; b1r[j] = b1g[cr]; b2r[j] = b2g[cr]; bgr[j] = bg[cr];
        agu[j] = ag[cu]; b1u[j] = b1g[cu]; b2u[j] = b2g[cu]; bgu[j] = bg[cu];
        acv[j] = ac[cr]; b1cv[j] = b1c[cr]; b2cv[j] = b2c[cr]; bcvv[j] = bcv[cr];
    }

    const int srow = tid & 127;
    const int scb  = (tid >> 7) * 8;
    const uint32_t sdst_off = (uint32_t)(srow * 272 + scb * 16);

    {
        float4 z = make_float4(0.f, 0.f, 0.f, 0.f);
        __stcg((float4*)(g_h + cta * 1024 + tid * 4), z);
        uint2 zb = make_uint2(0u, 0u);
        __stcg((uint2*)(g_hb + cta * 1024 + tid * 4), zb);
    }
    unsigned bar = barBase + 1;
    gsync(bar);

    for (int t = 0; t < TD; t++) {
        const float* Xt = XGC + (size_t)t * BD * NG;
        float ur[2][2];
        float2 hvp[2];

        // ================= gate phase =================
        {
            float2 gxr[2], gxu[2];
            #pragma unroll
            for (int half = 0; half < 2; half++) {
                int row = r0 + half * 8;
                gxr[half] = __ldcg((const float2*)(Xt + (size_t)row * NG + col0 + ecol));
                gxu[half] = __ldcg((const float2*)(Xt + (size_t)row * NG + 1024 + col0 + ecol));
                hvp[half] = __ldcg((const float2*)(g_h + (size_t)row * 1024 + col0 + ecol));
            }

            float acc[2][4];
            #pragma unroll
            for (int nt = 0; nt < 2; nt++)
                #pragma unroll
                for (int q = 0; q < 4; q++) acc[nt][q] = 0.f;

            #pragma unroll
            for (int p = 0; p < 3; p++) {
                const __nv_bfloat16* src = g_hb + (size_t)srow * 1024 + p * 128 + scb * 8;
                uint32_t dst = stB + (uint32_t)p * 34816u + sdst_off;
                #pragma unroll
                for (int c = 0; c < 8; c++) cp16(dst + c * 16, src + c * 8);
                CP_COMMIT();
            }
            for (int chunk = 0; chunk < 8; chunk++) {
                if (chunk < 5) {
                    const __nv_bfloat16* src = g_hb + (size_t)srow * 1024 + (chunk + 3) * 128 + scb * 8;
                    uint32_t dst = stB + (uint32_t)((chunk + 3) & 3) * 34816u + sdst_off;
                    #pragma unroll
                    for (int c = 0; c < 8; c++) cp16(dst + c * 16, src + c * 8);
                    CP_COMMIT();
                    CP_WAIT(3);
                } else {
                    CP_WAIT(0);
                }
                __syncthreads();
                uint32_t aB = stB + (uint32_t)(chunk & 3) * 34816u;
                #pragma unroll
                for (int ks = 0; ks < 8; ks++) {
                    int kloc = ks * 16;
                    int kg = chunk * 128 + kloc;
                    uint32_t af[4];
                    ldmatrix_x4(af[0], af[1], af[2], af[3],
                        aB + (uint32_t)((wid * 16 + arow_l) * 272 + (kloc + acol_l) * 2));
                    uint32_t bf[4];
                    ldmatrix_x4(bf[0], bf[1], bf[2], bf[3],
                        wgB + (uint32_t)(brow_l * 2064 + (kg + bcol_l) * 2));
                    mma16816(acc[0], af, &bf[0]);
                    mma16816(acc[1], af, &bf[2]);
                }
                __syncthreads();
            }

            #pragma unroll
            for (int half = 0; half < 2; half++) {
                int row = r0 + half * 8;
                float gh0 = acc[0][half * 2 + 0], gh1 = acc[0][half * 2 + 1];
                float z0 = agr[0] * gxr[half].x * gh0 + b1r[0] * gxr[half].x + b2r[0] * gh0 + bgr[0];
                float z1 = agr[1] * gxr[half].y * gh1 + b1r[1] * gxr[half].y + b2r[1] * gh1 + bgr[1];
                float s0 = 1.f / (1.f + expf(-z0));
                float s1 = 1.f / (1.f + expf(-z1));
                __nv_bfloat162 p = __floats2bfloat162_rn(s0 * hvp[half].x, s1 * hvp[half].y);
                __stcg((uint32_t*)(g_RHb + (size_t)row * 1024 + col0 + ecol), *(uint32_t*)&p);

                float uh0 = acc[1][half * 2 + 0], uh1 = acc[1][half * 2 + 1];
                float y0 = agu[0] * gxu[half].x * uh0 + b1u[0] * gxu[half].x + b2u[0] * uh0 + bgu[0];
                float y1 = agu[1] * gxu[half].y * uh1 + b1u[1] * gxu[half].y + b2u[1] * uh1 + bgu[1];
                ur[half][0] = 1.f / (1.f + expf(-y0));
                ur[half][1] = 1.f / (1.f + expf(-y1));
            }
        }
        bar++; gsync(bar);

        // ================= cand phase =================
        {
            float2 cxv[2];
            #pragma unroll
            for (int half = 0; half < 2; half++) {
                int row = r0 + half * 8;
                cxv[half] = __ldcg((const float2*)(Xt + (size_t)row * NG + 2048 + col0 + ecol));
            }

            float acc[4] = {0.f, 0.f, 0.f, 0.f};
            #pragma unroll
            for (int p = 0; p < 3; p++) {
                const __nv_bfloat16* src = g_RHb + (size_t)srow * 1024 + p * 128 + scb * 8;
                uint32_t dst = stB + (uint32_t)p * 34816u + sdst_off;
                #pragma unroll
                for (int c = 0; c < 8; c++) cp16(dst + c * 16, src + c * 8);
                CP_COMMIT();
            }
            for (int chunk = 0; chunk < 8; chunk++) {
                if (chunk < 5) {
                    const __nv_bfloat16* src = g_RHb + (size_t)srow * 1024 + (chunk + 3) * 128 + scb * 8;
                    uint32_t dst = stB + (uint32_t)((chunk + 3) & 3) * 34816u + sdst_off;
                    #pragma unroll
                    for (int c = 0; c < 8; c++) cp16(dst + c * 16, src + c * 8);
                    CP_COMMIT();
                    CP_WAIT(3);
                } else {
                    CP_WAIT(0);
                }
                __syncthreads();
                uint32_t aB = stB + (uint32_t)(chunk & 3) * 34816u;
                #pragma unroll
                for (int ks = 0; ks < 8; ks++) {
                    int kloc = ks * 16;
                    int kg = chunk * 128 + kloc;
                    uint32_t af[4];
                    ldmatrix_x4(af[0], af[1], af[2], af[3],
                        aB + (uint32_t)((wid * 16 + arow_l) * 272 + (kloc + acol_l) * 2));
                    uint32_t bf2[2];
                    ldmatrix_x2(bf2[0], bf2[1],
                        wcB + (uint32_t)((l16 & 7) * 2064 + (kg + (l16 >> 3) * 8) * 2));
                    mma16816(acc, af, bf2);
                }
                __syncthreads();
            }

            #pragma unroll
            for (int half = 0; half < 2; half++) {
                int row = r0 + half * 8;
                float ch0 = acc[half * 2 + 0], ch1 = acc[half * 2 + 1];
                float z0 = acv[0] * cxv[half].x * ch0 + b1cv[0] * cxv[half].x + b2cv[0] * ch0 + bcvv[0];
                float z1 = acv[1] * cxv[half].y * ch1 + b1cv[1] * cxv[half].y + b2cv[1] * ch1 + bcvv[1];
                float c0 = tanhf(z0), c1 = tanhf(z1);
                float hn0 = ur[half][0] * hvp[half].x + (1.f - ur[half][0]) * c0;
                float hn1 = ur[half][1] * hvp[half].y + (1.f - ur[half][1]) * c1;
                __stcg((float2*)(g_h + (size_t)row * 1024 + col0 + ecol), make_float2(hn0, hn1));
                __nv_bfloat162 p = __floats2bfloat162_rn(hn0, hn1);
                __stcg((uint32_t*)(g_hb + (size_t)row * 1024 + col0 + ecol), *(uint32_t*)&p);
                size_t off = (size_t)t * BD * HD + (size_t)row * HD + col0 + ecol;
                if (OM == 0)
                    *(__nv_bfloat162*)(outB + off) = p;
                else
                    *(float2*)(outF + off) = make_float2(hn0, hn1);
            }
        }
        bar++; gsync(bar);
    }
}

// ---------------- NCE ----------------
__global__ __launch_bounds__(256)
void k_nce_samp(float* __restrict__ outsum)
{
    __shared__ float As[8][132];
    __shared__ float Bs[8][64];
    __shared__ float red[256];
    const int tid = threadIdx.x;
    const int rowBase = blockIdx.x * 128;

    const int arow = tid >> 1;
    const int acol = (tid & 1) << 2;
    int gi = rowBase + arow;
    size_t aoff = (size_t)((gi & 255) * BD + (gi >> 8)) * HD;

    const int brow = tid >> 5;
    const int bcl  = (tid & 31) << 1;
    const int ty = tid >> 4;
    const int tx = tid & 15;

    float acc[8][4];
    #pragma unroll
    for (int i = 0; i < 8; i++)
        #pragma unroll
        for (int j = 0; j < 4; j++) acc[i][j] = 0.f;

    for (int k0 = 0; k0 < HD; k0 += 8) {
        float4 av = *(const float4*)(g_O1 + aoff + k0 + acol);
        As[acol + 0][arow] = av.x;
        As[acol + 1][arow] = av.y;
        As[acol + 2][arow] = av.z;
        As[acol + 3][arow] = av.w;
        float2 bw = *(const float2*)(g_sampWT + (size_t)(k0 + brow) * SD + bcl);
        Bs[brow][bcl]     = bw.x;
        Bs[brow][bcl + 1] = bw.y;
        __syncthreads();
        #pragma unroll
        for (int k = 0; k < 8; k++) {
            float ar[8], br[4];
            *(float4*)&ar[0] = *(const float4*)&As[k][ty * 8];
            *(float4*)&ar[4] = *(const float4*)&As[k][ty * 8 + 4];
            *(float4*)&br[0] = *(const float4*)&Bs[k][tx * 4];
            #pragma unroll
            for (int i = 0; i < 8; i++)
                #pragma unroll
                for (int j = 0; j < 4; j++)
                    acc[i][j] += ar[i] * br[j];
        }
        __syncthreads();
    }

    float s = 0.f;
    #pragma unroll
    for (int j = 0; j < 4; j++) {
        float sbv = g_sampB[tx * 4 + j];
        #pragma unroll
        for (int i = 0; i < 8; i++)
            s += softplusf(acc[i][j] + sbv);
    }
    red[tid] = s;
    __syncthreads();
    for (int o = 128; o > 0; o >>= 1) {
        if (tid < o) red[tid] += red[tid + o];
        __syncthreads();
    }
    if (tid == 0) atomicAdd(outsum, red[0] * (1.f / 32768.f));
}

__global__ __launch_bounds__(256)
void k_nce_true(const int* __restrict__ targets, const float* __restrict__ sw,
                const float* __restrict__ sb, float* __restrict__ outsum)
{
    __shared__ float red[8];
    const int warp = threadIdx.x >> 5;
    const int lane = threadIdx.x & 31;
    const int i = blockIdx.x * 8 + warp;
    const int label = targets[i];
    const float* orow = g_O1 + (size_t)((i & 255) * BD + (i >> 8)) * HD;
    const float* wrow = sw + (size_t)label * HD;

    float s = 0.f;
    #pragma unroll
    for (int k0 = 0; k0 < HD; k0 += 128) {
        float4 a = *(const float4*)(orow + k0 + lane * 4);
        float4 w = *(const float4*)(wrow + k0 + lane * 4);
        s += a.x * w.x + a.y * w.y + a.z * w.z + a.w * w.w;
    }
    #pragma unroll
    for (int o = 16; o > 0; o >>= 1) s += __shfl_xor_sync(0xffffffffu, s, o);
    if (lane == 0) {
        float logit = s + sb[label];
        red[warp] = softplusf(-logit);
    }
    __syncthreads();
    if (threadIdx.x == 0) {
        float t = 0.f;
        #pragma unroll
        for (int w = 0; w < 8; w++) t += red[w];
        atomicAdd(outsum, t * (1.f / 32768.f));
    }
}

// ---------------- launch ----------------
extern "C" void kernel_launch(void* const* d_in, const int* in_sizes, int n_in,
                              void* d_out, int out_size)
{
    const int*   input_data = (const int*)  d_in[0];
    const int*   targets    = (const int*)  d_in[1];
    const int*   nce        = (const int*)  d_in[2];
    const float* embedding  = (const float*)d_in[3];
    const float* win        = (const float*)d_in[4];
    const float* bin_       = (const float*)d_in[5];
    const float* Wxg        = (const float*)d_in[6];
    const float* Whg        = (const float*)d_in[7];
    const float* ag         = (const float*)d_in[8];
    const float* b1g        = (const float*)d_in[9];
    const float* b2g        = (const float*)d_in[10];
    const float* bg         = (const float*)d_in[11];
    const float* Wxc        = (const float*)d_in[12];
    const float* Whc        = (const float*)d_in[13];
    const float* ac         = (const float*)d_in[14];
    const float* b1c        = (const float*)d_in[15];
    const float* b2c        = (const float*)d_in[16];
    const float* bc         = (const float*)d_in[17];
    const float* softmax_w  = (const float*)d_in[18];
    const float* softmax_b  = (const float*)d_in[19];
    float* out = (float*)d_out;

    float *pXGC0, *pXGC1, *pO1;
    int* pidx;
    __nv_bfloat16 *pAb, *pEb, *pWbTw, *pWbT0, *pO0b;
    cudaGetSymbolAddress((void**)&pXGC0, g_XGC0);
    cudaGetSymbolAddress((void**)&pXGC1, g_XGC1);
    cudaGetSymbolAddress((void**)&pO1,  g_O1);
    cudaGetSymbolAddress((void**)&pO0b, g_O0b);
    cudaGetSymbolAddress((void**)&pidx, g_rowidx);
    cudaGetSymbolAddress((void**)&pAb,  g_Ab);
    cudaGetSymbolAddress((void**)&pEb,  g_Eb);
    cudaGetSymbolAddress((void**)&pWbTw, g_WbTw);
    cudaGetSymbolAddress((void**)&pWbT0, g_WbT0);

    cudaFuncSetAttribute((const void*)k_layerX<0, 24>,
                         cudaFuncAttributeMaxDynamicSharedMemorySize, 188800);
    cudaFuncSetAttribute((const void*)k_layerX<1, 0>,
                         cudaFuncAttributeMaxDynamicSharedMemorySize, 188800);

    // launch 0: setup + embedding->bf16 + all weight transposes
    k_convW<<<128 + 16384 + 1024 + 3072 + 3072, 256>>>(
        input_data, out, out_size, embedding, win, Wxg, Wxc);

    // launch 1: X(bf16) = gather(Eb) @ win + bin_   -> g_Ab
    k_mgemm<true, true, true><<<dim3(HD / 128, TB / 128), 256>>>(
        pEb, pWbTw, bin_, nullptr, pAb, HD, pidx);

    // launch 2: XGC0 = Ab @ [Wxg0|Wxc0]
    k_mgemm<false, false, false><<<dim3(NG / 128, TB / 128), 256>>>(
        pAb, pWbT0, nullptr, pXGC0, nullptr, NG, nullptr);

    // launch 3: layer-0 recurrence (128 CTAs) + 24 fused XGC1 GEMM workers
    k_layerX<0, 24><<<152, 256, 188800>>>(
        Whg, Whc, pXGC0,
        ag, b1g, b2g, bg, ac, b1c, b2c, bc,
        nullptr, pO0b, 0u);

    // launch 4: layer-1 recurrence (XGC1 already produced by workers)
    k_layerX<1, 0><<<128, 256, 188800>>>(
        Whg + (size_t)HD * H2, Whc + (size_t)HD * HD, pXGC1,
        ag + H2, b1g + H2, b2g + H2, bg + H2,
        ac + HD, b1c + HD, b2c + HD, bc + HD,
        pO1, nullptr, 1u + 2u * TD);

    // NCE
    k_gather_samp<<<SD, 256>>>(nce, softmax_w, softmax_b);
    k_nce_true<<<TB / 8, 256>>>(targets, softmax_w, softmax_b, out);
    k_nce_samp<<<TB / 128, 256>>>(out);
}